// round 1
// baseline (speedup 1.0000x reference)
#include <cuda_runtime.h>
#include <math.h>

// ---------------------------------------------------------------------------
// Problem constants
// ---------------------------------------------------------------------------
namespace {
constexpr int Dm   = 768;
constexpr int FFm  = 3072;
constexpr int Hm   = 12;
constexpr int Lm   = 3;
constexpr int CSm  = 512;
constexpr int Bm   = 256;
constexpr int Cm   = 32;
constexpr int NSEQ = Bm * Cm * 2;   // 16384 sequences of 2 tokens
constexpr int TT   = NSEQ * 2;      // 32768 tokens
constexpr float EPSf = 1e-5f;
}

// ---------------------------------------------------------------------------
// Scratch (device globals; no runtime allocation allowed)
// ---------------------------------------------------------------------------
__device__ float g_x   [TT * Dm];        // token states          (25.2M)
__device__ float g_tmp1[TT * Dm];        // qk_in / attn-out / lh
__device__ float g_qk  [TT * 2 * Dm];    // [Q|K] proj / rc       (50.3M)
__device__ float g_v   [TT * Dm];        // V proj / rh
__device__ float g_t   [TT * Dm];        // proj results / lc
__device__ float g_hid [TT * FFm];       // MLP hidden / ph,pc    (100.7M)

__device__ __forceinline__ float gelu_f(float x) {
    return 0.5f * x * (1.0f + erff(x * 0.7071067811865475f));
}

// ---------------------------------------------------------------------------
// Generic NT GEMM:  C[M,N] = A[M,K] @ B[N,K]^T + bias[N]   (optional GELU)
// Tiles: BM=BN=128, BK=16, 256 threads, 8x8 per-thread register tile.
// All M,N multiples of 128 and K multiples of 16 in this problem -> no guards.
// ---------------------------------------------------------------------------
template <bool GELU>
__global__ void __launch_bounds__(256) gemm_nt(
    const float* __restrict__ A, int lda,
    const float* __restrict__ B,              // ldb == K (row-major weights)
    const float* __restrict__ bias,
    float* __restrict__ C, int ldc, int K)
{
    constexpr int BM = 128, BN = 128, BK = 16;
    __shared__ float As[BK * BM];
    __shared__ float Bs[BK * BN];

    const int bm  = blockIdx.y * BM;
    const int bn  = blockIdx.x * BN;
    const int tid = threadIdx.x;
    const int lr  = tid >> 2;          // 0..63
    const int lc4 = (tid & 3) << 2;    // 0,4,8,12

    const float* Ap = A + (size_t)(bm + lr) * lda + lc4;
    const float* Bp = B + (size_t)(bn + lr) * K   + lc4;

    const int ty = tid >> 4;           // 0..15
    const int tx = tid & 15;           // 0..15

    float acc[8][8];
#pragma unroll
    for (int i = 0; i < 8; i++)
#pragma unroll
        for (int j = 0; j < 8; j++) acc[i][j] = 0.f;

    for (int k0 = 0; k0 < K; k0 += BK) {
        float4 a0 = *(const float4*)(Ap);
        float4 a1 = *(const float4*)(Ap + (size_t)64 * lda);
        float4 b0 = *(const float4*)(Bp);
        float4 b1 = *(const float4*)(Bp + (size_t)64 * K);

        As[(lc4 + 0) * BM + lr]      = a0.x;
        As[(lc4 + 1) * BM + lr]      = a0.y;
        As[(lc4 + 2) * BM + lr]      = a0.z;
        As[(lc4 + 3) * BM + lr]      = a0.w;
        As[(lc4 + 0) * BM + lr + 64] = a1.x;
        As[(lc4 + 1) * BM + lr + 64] = a1.y;
        As[(lc4 + 2) * BM + lr + 64] = a1.z;
        As[(lc4 + 3) * BM + lr + 64] = a1.w;

        Bs[(lc4 + 0) * BN + lr]      = b0.x;
        Bs[(lc4 + 1) * BN + lr]      = b0.y;
        Bs[(lc4 + 2) * BN + lr]      = b0.z;
        Bs[(lc4 + 3) * BN + lr]      = b0.w;
        Bs[(lc4 + 0) * BN + lr + 64] = b1.x;
        Bs[(lc4 + 1) * BN + lr + 64] = b1.y;
        Bs[(lc4 + 2) * BN + lr + 64] = b1.z;
        Bs[(lc4 + 3) * BN + lr + 64] = b1.w;

        __syncthreads();

#pragma unroll
        for (int k = 0; k < BK; k++) {
            float ar[8], br[8];
#pragma unroll
            for (int i = 0; i < 8; i++) ar[i] = As[k * BM + ty * 8 + i];
#pragma unroll
            for (int j = 0; j < 8; j++) br[j] = Bs[k * BN + tx * 8 + j];
#pragma unroll
            for (int i = 0; i < 8; i++)
#pragma unroll
                for (int j = 0; j < 8; j++) acc[i][j] += ar[i] * br[j];
        }
        __syncthreads();

        Ap += BK;
        Bp += BK;
    }

    // Epilogue: bias (+ optional exact GELU), vectorized stores
    float bv[8];
#pragma unroll
    for (int j = 0; j < 8; j++) bv[j] = bias[bn + tx * 8 + j];

#pragma unroll
    for (int i = 0; i < 8; i++) {
        float* crow = C + (size_t)(bm + ty * 8 + i) * ldc + bn + tx * 8;
#pragma unroll
        for (int jj = 0; jj < 8; jj += 4) {
            float4 r;
            r.x = acc[i][jj + 0] + bv[jj + 0];
            r.y = acc[i][jj + 1] + bv[jj + 1];
            r.z = acc[i][jj + 2] + bv[jj + 2];
            r.w = acc[i][jj + 3] + bv[jj + 3];
            if (GELU) {
                r.x = gelu_f(r.x); r.y = gelu_f(r.y);
                r.z = gelu_f(r.z); r.w = gelu_f(r.w);
            }
            *(float4*)(crow + jj) = r;
        }
    }
}

// ---------------------------------------------------------------------------
// x construction: token 2n = parent[b], token 2n+1 = child[n^1]  (flip of k)
// ---------------------------------------------------------------------------
__global__ void build_x(const float* __restrict__ parent,
                        const float* __restrict__ child)
{
    int idx = blockIdx.x * blockDim.x + threadIdx.x;
    if (idx >= TT * Dm) return;
    int t = idx / Dm;
    int d = idx - t * Dm;
    int n = t >> 1;
    float val;
    if ((t & 1) == 0) {
        int b = n >> 6;                       // n / (C*2), C=32
        val = parent[b * Dm + d];
    } else {
        val = child[(size_t)(n ^ 1) * Dm + d];
    }
    g_x[idx] = val;
}

// qk_in = x + pos_emb[l][role];  role: token0->0, token1-> 1+k
__global__ void add_pe(const float* __restrict__ pe_l)
{
    int idx = blockIdx.x * blockDim.x + threadIdx.x;
    if (idx >= TT * Dm) return;
    int t = idx / Dm;
    int d = idx - t * Dm;
    int role = (t & 1) ? (1 + ((t >> 1) & 1)) : 0;
    g_tmp1[idx] = g_x[idx] + pe_l[role * Dm + d];
}

// ---------------------------------------------------------------------------
// 2x2 attention per (sequence, head).  One warp per (n,h); lane owns 2 dims.
// Q at g_qk[:, 0:768], K at g_qk[:, 768:1536], V in g_v.  Output -> g_tmp1.
// ---------------------------------------------------------------------------
__global__ void attn2()
{
    int gw   = (blockIdx.x * blockDim.x + threadIdx.x) >> 5;
    int lane = threadIdx.x & 31;
    if (gw >= NSEQ * Hm) return;
    int n = gw / Hm;
    int h = gw - n * Hm;

    size_t qbase = (size_t)(2 * n) * (2 * Dm) + h * 64 + 2 * lane;
    float2 q0 = *(const float2*)(g_qk + qbase);
    float2 k0 = *(const float2*)(g_qk + qbase + Dm);
    float2 q1 = *(const float2*)(g_qk + qbase + 2 * Dm);
    float2 k1 = *(const float2*)(g_qk + qbase + 3 * Dm);

    size_t vbase = (size_t)(2 * n) * Dm + h * 64 + 2 * lane;
    float2 v0 = *(const float2*)(g_v + vbase);
    float2 v1 = *(const float2*)(g_v + vbase + Dm);

    float s00 = q0.x * k0.x + q0.y * k0.y;
    float s01 = q0.x * k1.x + q0.y * k1.y;
    float s10 = q1.x * k0.x + q1.y * k0.y;
    float s11 = q1.x * k1.x + q1.y * k1.y;
#pragma unroll
    for (int o = 16; o; o >>= 1) {
        s00 += __shfl_xor_sync(0xffffffffu, s00, o);
        s01 += __shfl_xor_sync(0xffffffffu, s01, o);
        s10 += __shfl_xor_sync(0xffffffffu, s10, o);
        s11 += __shfl_xor_sync(0xffffffffu, s11, o);
    }
    const float sc = 0.125f;                    // 1/sqrt(64)
    s00 *= sc; s01 *= sc; s10 *= sc; s11 *= sc;

    float m0 = fmaxf(s00, s01), m1 = fmaxf(s10, s11);
    float e00 = __expf(s00 - m0), e01 = __expf(s01 - m0);
    float e10 = __expf(s10 - m1), e11 = __expf(s11 - m1);
    float r0 = 1.f / (e00 + e01), r1 = 1.f / (e10 + e11);
    float a00 = e00 * r0, a01 = e01 * r0;
    float a10 = e10 * r1, a11 = e11 * r1;

    float2 o0, o1;
    o0.x = a00 * v0.x + a01 * v1.x;  o0.y = a00 * v0.y + a01 * v1.y;
    o1.x = a10 * v0.x + a11 * v1.x;  o1.y = a10 * v0.y + a11 * v1.y;
    *(float2*)(g_tmp1 + vbase)      = o0;
    *(float2*)(g_tmp1 + vbase + Dm) = o1;
}

// ---------------------------------------------------------------------------
// Block reduction (256 threads)
// ---------------------------------------------------------------------------
__device__ __forceinline__ float block_sum(float v)
{
    __shared__ float red[8];
    __shared__ float total;
    int lane = threadIdx.x & 31, w = threadIdx.x >> 5;
#pragma unroll
    for (int o = 16; o; o >>= 1) v += __shfl_xor_sync(0xffffffffu, v, o);
    __syncthreads();                 // protect shared reuse across calls
    if (lane == 0) red[w] = v;
    __syncthreads();
    if (threadIdx.x == 0) {
        float s = 0.f;
#pragma unroll
        for (int i = 0; i < 8; i++) s += red[i];
        total = s;
    }
    __syncthreads();
    return total;
}

// x[row] = inorm(x[row] + delta[row]) over D=768. One block per row.
__global__ void add_inorm(float* __restrict__ x, const float* __restrict__ delta)
{
    int row = blockIdx.x;
    int tid = threadIdx.x;
    size_t base = (size_t)row * Dm;
    float vals[3];
    float s = 0.f;
#pragma unroll
    for (int i = 0; i < 3; i++) {
        int c = tid + i * 256;
        vals[i] = x[base + c] + delta[base + c];
        s += vals[i];
    }
    float mean = block_sum(s) * (1.f / 768.f);
    float vs = 0.f;
#pragma unroll
    for (int i = 0; i < 3; i++) {
        float d = vals[i] - mean;
        vs += d * d;
    }
    float var = block_sum(vs) * (1.f / 768.f);
    float rs = rsqrtf(var + EPSf);
#pragma unroll
    for (int i = 0; i < 3; i++)
        x[base + tid + i * 256] = (vals[i] - mean) * rs;
}

// out_e[n] = inorm(x[2n] + x[2n+1]).  One block per sequence.
__global__ void final_out(float* __restrict__ out)
{
    int n = blockIdx.x;
    int tid = threadIdx.x;
    size_t base = (size_t)(2 * n) * Dm;
    float vals[3];
    float s = 0.f;
#pragma unroll
    for (int i = 0; i < 3; i++) {
        int c = tid + i * 256;
        vals[i] = g_x[base + c] + g_x[base + Dm + c];
        s += vals[i];
    }
    float mean = block_sum(s) * (1.f / 768.f);
    float vs = 0.f;
#pragma unroll
    for (int i = 0; i < 3; i++) {
        float d = vals[i] - mean;
        vs += d * d;
    }
    float var = block_sum(vs) * (1.f / 768.f);
    float rs = rsqrtf(var + EPSf);
#pragma unroll
    for (int i = 0; i < 3; i++)
        out[(size_t)n * Dm + tid + i * 256] = (vals[i] - mean) * rs;
}

// outside scores: out[i*2+0] = <pc[b], rc[i]>/sqrt(CS), out[i*2+1] = <pc[b], lc[i]>/sqrt(CS)
__global__ void dot_scores(const float* __restrict__ pc,
                           const float* __restrict__ lc,
                           const float* __restrict__ rc,
                           float* __restrict__ out)
{
    int gw   = (blockIdx.x * blockDim.x + threadIdx.x) >> 5;
    int lane = threadIdx.x & 31;
    if (gw >= NSEQ) return;
    int i     = gw >> 1;
    int which = gw & 1;
    int b     = i >> 5;                      // i / C, C=32
    const float* u = pc + b * CSm;
    const float* w = (which == 0 ? rc : lc) + (size_t)i * CSm;
    float s = 0.f;
#pragma unroll 4
    for (int j = lane; j < CSm; j += 32) s += u[j] * w[j];
#pragma unroll
    for (int o = 16; o; o >>= 1) s += __shfl_xor_sync(0xffffffffu, s, o);
    if (lane == 0) out[gw] = s * 0.044194173824159216f;   // 1/sqrt(512)
}

// ---------------------------------------------------------------------------
// Host launcher
// ---------------------------------------------------------------------------
static float* devptr(const void* sym)
{
    void* p = nullptr;
    cudaGetSymbolAddress(&p, sym);
    return (float*)p;
}

extern "C" void kernel_launch(void* const* d_in, const int* in_sizes, int n_in,
                              void* d_out, int out_size)
{
    (void)in_sizes; (void)n_in; (void)out_size;

    const float* parent     = (const float*)d_in[0];
    const float* child      = (const float*)d_in[1];
    // d_in[2] parent_scores, d_in[3] child_scores: unused by reference
    const float* attn_in_w  = (const float*)d_in[4];
    const float* attn_in_b  = (const float*)d_in[5];
    const float* attn_out_w = (const float*)d_in[6];
    const float* attn_out_b = (const float*)d_in[7];
    const float* lin1_w     = (const float*)d_in[8];
    const float* lin1_b     = (const float*)d_in[9];
    const float* lin2_w     = (const float*)d_in[10];
    const float* lin2_b     = (const float*)d_in[11];
    const float* pos_emb    = (const float*)d_in[12];
    const float* parent_w1  = (const float*)d_in[13];
    const float* parent_b1  = (const float*)d_in[14];
    const float* parent_w2  = (const float*)d_in[15];
    const float* parent_b2  = (const float*)d_in[16];
    const float* left_w1    = (const float*)d_in[17];
    const float* left_b1    = (const float*)d_in[18];
    const float* left_w2    = (const float*)d_in[19];
    const float* left_b2    = (const float*)d_in[20];
    const float* right_w1   = (const float*)d_in[21];
    const float* right_b1   = (const float*)d_in[22];
    const float* right_w2   = (const float*)d_in[23];
    const float* right_b2   = (const float*)d_in[24];
    float* out = (float*)d_out;

    float* px   = devptr(g_x);
    float* ptmp = devptr(g_tmp1);
    float* pqk  = devptr(g_qk);
    float* pv   = devptr(g_v);
    float* pt   = devptr(g_t);
    float* phid = devptr(g_hid);

    const int EW = (TT * Dm) / 256;          // elementwise grid

    // ---- token state init ----
    build_x<<<EW, 256>>>(parent, child);

    // ---- outside-score path (reuses layer scratch; runs before layers) ----
    {
        dim3 gP (Dm  / 128, Bm / 128);
        dim3 gP2(CSm / 128, Bm / 128);
        dim3 gC (Dm  / 128, 8192 / 128);
        dim3 gC2(CSm / 128, 8192 / 128);
        // ph = gelu(parent @ pw1^T + pb1); pc = ph @ pw2^T + pb2
        gemm_nt<true ><<<gP , 256>>>(parent, Dm, parent_w1, parent_b1, phid,            Dm,  Dm);
        gemm_nt<false><<<gP2, 256>>>(phid,   Dm, parent_w2, parent_b2, phid + Bm * Dm,  CSm, Dm);
        // lc from left children (rows 2i of child), rc from right children (rows 2i+1)
        gemm_nt<true ><<<gC , 256>>>(child,      2 * Dm, left_w1,  left_b1,  ptmp, Dm,  Dm);
        gemm_nt<false><<<gC2, 256>>>(ptmp,       Dm,     left_w2,  left_b2,  pt,   CSm, Dm);
        gemm_nt<true ><<<gC , 256>>>(child + Dm, 2 * Dm, right_w1, right_b1, pv,   Dm,  Dm);
        gemm_nt<false><<<gC2, 256>>>(pv,         Dm,     right_w2, right_b2, pqk,  CSm, Dm);
        dot_scores<<<(NSEQ * 32) / 256, 256>>>(phid + Bm * Dm, pt, pqk, out);
    }

    // ---- 3 tree-transformer layers ----
    dim3 gQK(1536 / 128, TT / 128);
    dim3 gD (Dm   / 128, TT / 128);
    dim3 gM1(FFm  / 128, TT / 128);

    for (int l = 0; l < Lm; l++) {
        const float* iw = attn_in_w  + (size_t)l * 3 * Dm * Dm;
        const float* ib = attn_in_b  + (size_t)l * 3 * Dm;
        const float* ow = attn_out_w + (size_t)l * Dm * Dm;
        const float* ob = attn_out_b + (size_t)l * Dm;
        const float* w1 = lin1_w     + (size_t)l * FFm * Dm;
        const float* b1 = lin1_b     + (size_t)l * FFm;
        const float* w2 = lin2_w     + (size_t)l * Dm * FFm;
        const float* b2 = lin2_b     + (size_t)l * Dm;

        add_pe<<<EW, 256>>>(pos_emb + (size_t)l * 4 * Dm);
        // [Q|K] = (x+pe) @ [Wq;Wk]^T + [bq;bk]   -> g_qk (ldc = 1536)
        gemm_nt<false><<<gQK, 256>>>(ptmp, Dm, iw,               ib,            pqk, 2 * Dm, Dm);
        // V = x @ Wv^T + bv                      -> g_v
        gemm_nt<false><<<gD , 256>>>(px,   Dm, iw + 2 * Dm * Dm, ib + 2 * Dm,   pv,  Dm,     Dm);
        attn2<<<(NSEQ * Hm * 32) / 256, 256>>>();
        // out-proj -> g_t, then x = inorm(x + g_t)
        gemm_nt<false><<<gD , 256>>>(ptmp, Dm, ow, ob, pt, Dm, Dm);
        add_inorm<<<TT, 256>>>(px, pt);
        // MLP: hid = gelu(x @ w1^T + b1); f = hid @ w2^T + b2; x = inorm(x + f)
        gemm_nt<true ><<<gM1, 256>>>(px,   Dm,  w1, b1, phid, FFm, Dm);
        gemm_nt<false><<<gD , 256>>>(phid, FFm, w2, b2, pt,   Dm,  FFm);
        add_inorm<<<TT, 256>>>(px, pt);
    }

    // ---- final: out_e_ij = inorm(token0 + token1) ----
    final_out<<<NSEQ, 256>>>(out + NSEQ);
}

// round 2
// speedup vs baseline: 2.8658x; 2.8658x over previous
#include <cuda_runtime.h>
#include <math.h>
#include <stdint.h>

// ---------------------------------------------------------------------------
// Problem constants
// ---------------------------------------------------------------------------
namespace {
constexpr int Dm   = 768;
constexpr int FFm  = 3072;
constexpr int Hm   = 12;
constexpr int Lm   = 3;
constexpr int CSm  = 512;
constexpr int Bm   = 256;
constexpr int NSEQ = 16384;         // B*C*2 sequences of 2 tokens
constexpr int TT   = NSEQ * 2;      // 32768 tokens
constexpr float EPSf = 1e-5f;
}

// ---------------------------------------------------------------------------
// Scratch (device globals; no runtime allocation allowed)
// ---------------------------------------------------------------------------
__device__ float g_x   [TT * Dm];
__device__ float g_tmp1[TT * Dm];
__device__ float g_qk  [TT * 2 * Dm];
__device__ float g_v   [TT * Dm];
__device__ float g_t   [TT * Dm];
__device__ float g_hid [TT * FFm];

__device__ __forceinline__ float gelu_f(float x) {
    return 0.5f * x * (1.0f + erff(x * 0.7071067811865475f));
}

__device__ __forceinline__ float to_tf32(float x) {
    uint32_t u;
    asm("cvt.rna.tf32.f32 %0, %1;" : "=r"(u) : "f"(x));
    return __uint_as_float(u);
}

// ---------------------------------------------------------------------------
// tf32 tensor-core NT GEMM:  C[M,N] = A[M,K] @ B[N,K]^T + bias[N]  (opt GELU)
// BM=BN=128, BK=16, 256 threads (8 warps, 4x2), warp tile 32x64,
// mma.sync.m16n8k8.tf32, fp32 accumulate. Double-buffered SMEM, reg-staged
// global loads with round-to-nearest tf32 conversion in the store path.
// All M,N multiples of 128 and K multiples of 16 in this problem.
// ---------------------------------------------------------------------------
template <bool GELU>
__global__ void __launch_bounds__(256) gemm_tf32(
    const float* __restrict__ A, int lda,
    const float* __restrict__ B,              // [N,K] row-major (ldb == K)
    const float* __restrict__ bias,
    float* __restrict__ C, int ldc, int K)
{
    constexpr int BM = 128, BN = 128, BK = 16, LDs = BK + 4;   // stride 20
    __shared__ float As[2][BM * LDs];
    __shared__ float Bs[2][BN * LDs];

    const int tid  = threadIdx.x;
    const int bm   = blockIdx.y * BM;
    const int bn   = blockIdx.x * BN;
    const int lane = tid & 31;
    const int wid  = tid >> 5;
    const int wm   = wid & 3;                  // 0..3 -> 32-row slab
    const int wn   = wid >> 2;                 // 0..1 -> 64-col slab
    const int g    = lane >> 2;                // 0..7
    const int tg   = lane & 3;                 // 0..3

    // gmem staging coords: each thread owns rows {r, r+64}, 4 cols at lc
    const int lrow = tid >> 2;                 // 0..63
    const int lc   = (tid & 3) << 2;           // 0,4,8,12
    const float* Ap = A + (size_t)(bm + lrow) * lda + lc;
    const float* Bp = B + (size_t)(bn + lrow) * K   + lc;

    float c[2][8][4];
#pragma unroll
    for (int mt = 0; mt < 2; mt++)
#pragma unroll
        for (int nt = 0; nt < 8; nt++)
#pragma unroll
            for (int j = 0; j < 4; j++) c[mt][nt][j] = 0.f;

    float4 fa0 = *(const float4*)(Ap);
    float4 fa1 = *(const float4*)(Ap + (size_t)64 * lda);
    float4 fb0 = *(const float4*)(Bp);
    float4 fb1 = *(const float4*)(Bp + (size_t)64 * K);

    auto store_tile = [&](int buf, float4 a0, float4 a1, float4 b0, float4 b1) {
        float4 t;
        t.x = to_tf32(a0.x); t.y = to_tf32(a0.y); t.z = to_tf32(a0.z); t.w = to_tf32(a0.w);
        *(float4*)&As[buf][lrow * LDs + lc] = t;
        t.x = to_tf32(a1.x); t.y = to_tf32(a1.y); t.z = to_tf32(a1.z); t.w = to_tf32(a1.w);
        *(float4*)&As[buf][(lrow + 64) * LDs + lc] = t;
        t.x = to_tf32(b0.x); t.y = to_tf32(b0.y); t.z = to_tf32(b0.z); t.w = to_tf32(b0.w);
        *(float4*)&Bs[buf][lrow * LDs + lc] = t;
        t.x = to_tf32(b1.x); t.y = to_tf32(b1.y); t.z = to_tf32(b1.z); t.w = to_tf32(b1.w);
        *(float4*)&Bs[buf][(lrow + 64) * LDs + lc] = t;
    };

    store_tile(0, fa0, fa1, fb0, fb1);
    __syncthreads();

    const int nk = K / BK;
    int buf = 0;

    for (int it = 0; it < nk; it++) {
        if (it + 1 < nk) {
            Ap += BK; Bp += BK;
            fa0 = *(const float4*)(Ap);
            fa1 = *(const float4*)(Ap + (size_t)64 * lda);
            fb0 = *(const float4*)(Bp);
            fb1 = *(const float4*)(Bp + (size_t)64 * K);
        }

        const float* as = As[buf];
        const float* bs = Bs[buf];
#pragma unroll
        for (int ks = 0; ks < 2; ks++) {
            const int k1 = ks * 8 + tg;
            uint32_t a[2][4], b[8][2];
#pragma unroll
            for (int mt = 0; mt < 2; mt++) {
                const int r = (wm * 32 + mt * 16 + g) * LDs;
                a[mt][0] = __float_as_uint(as[r + k1]);
                a[mt][1] = __float_as_uint(as[r + 8 * LDs + k1]);
                a[mt][2] = __float_as_uint(as[r + k1 + 4]);
                a[mt][3] = __float_as_uint(as[r + 8 * LDs + k1 + 4]);
            }
#pragma unroll
            for (int nt = 0; nt < 8; nt++) {
                const int r = (wn * 64 + nt * 8 + g) * LDs;
                b[nt][0] = __float_as_uint(bs[r + k1]);
                b[nt][1] = __float_as_uint(bs[r + k1 + 4]);
            }
#pragma unroll
            for (int mt = 0; mt < 2; mt++)
#pragma unroll
                for (int nt = 0; nt < 8; nt++) {
                    asm volatile(
                        "mma.sync.aligned.m16n8k8.row.col.f32.tf32.tf32.f32 "
                        "{%0,%1,%2,%3}, {%4,%5,%6,%7}, {%8,%9}, {%0,%1,%2,%3};"
                        : "+f"(c[mt][nt][0]), "+f"(c[mt][nt][1]),
                          "+f"(c[mt][nt][2]), "+f"(c[mt][nt][3])
                        : "r"(a[mt][0]), "r"(a[mt][1]), "r"(a[mt][2]), "r"(a[mt][3]),
                          "r"(b[nt][0]), "r"(b[nt][1]));
                }
        }

        if (it + 1 < nk) store_tile(buf ^ 1, fa0, fa1, fb0, fb1);
        __syncthreads();
        buf ^= 1;
    }

    // Epilogue: bias (+ optional exact GELU), float2 stores
#pragma unroll
    for (int mt = 0; mt < 2; mt++) {
        const int row = bm + wm * 32 + mt * 16 + g;
#pragma unroll
        for (int nt = 0; nt < 8; nt++) {
            const int col = bn + wn * 64 + nt * 8 + 2 * tg;
            const float bx = bias[col], by = bias[col + 1];
            float2 v0, v1;
            v0.x = c[mt][nt][0] + bx;  v0.y = c[mt][nt][1] + by;
            v1.x = c[mt][nt][2] + bx;  v1.y = c[mt][nt][3] + by;
            if (GELU) {
                v0.x = gelu_f(v0.x); v0.y = gelu_f(v0.y);
                v1.x = gelu_f(v1.x); v1.y = gelu_f(v1.y);
            }
            *(float2*)(C + (size_t)row * ldc + col)       = v0;
            *(float2*)(C + (size_t)(row + 8) * ldc + col) = v1;
        }
    }
}

// ---------------------------------------------------------------------------
// x construction: token 2n = parent[b], token 2n+1 = child[n^1]  (flip of k)
// ---------------------------------------------------------------------------
__global__ void build_x(const float* __restrict__ parent,
                        const float* __restrict__ child)
{
    int idx = blockIdx.x * blockDim.x + threadIdx.x;
    if (idx >= TT * Dm) return;
    int t = idx / Dm;
    int d = idx - t * Dm;
    int n = t >> 1;
    float val;
    if ((t & 1) == 0) {
        int b = n >> 6;
        val = parent[b * Dm + d];
    } else {
        val = child[(size_t)(n ^ 1) * Dm + d];
    }
    g_x[idx] = val;
}

__global__ void add_pe(const float* __restrict__ pe_l)
{
    int idx = blockIdx.x * blockDim.x + threadIdx.x;
    if (idx >= TT * Dm) return;
    int t = idx / Dm;
    int d = idx - t * Dm;
    int role = (t & 1) ? (1 + ((t >> 1) & 1)) : 0;
    g_tmp1[idx] = g_x[idx] + pe_l[role * Dm + d];
}

// ---------------------------------------------------------------------------
// 2x2 attention per (sequence, head). One warp per (n,h).
// ---------------------------------------------------------------------------
__global__ void attn2()
{
    int gw   = (blockIdx.x * blockDim.x + threadIdx.x) >> 5;
    int lane = threadIdx.x & 31;
    if (gw >= NSEQ * Hm) return;
    int n = gw / Hm;
    int h = gw - n * Hm;

    size_t qbase = (size_t)(2 * n) * (2 * Dm) + h * 64 + 2 * lane;
    float2 q0 = *(const float2*)(g_qk + qbase);
    float2 k0 = *(const float2*)(g_qk + qbase + Dm);
    float2 q1 = *(const float2*)(g_qk + qbase + 2 * Dm);
    float2 k1 = *(const float2*)(g_qk + qbase + 3 * Dm);

    size_t vbase = (size_t)(2 * n) * Dm + h * 64 + 2 * lane;
    float2 v0 = *(const float2*)(g_v + vbase);
    float2 v1 = *(const float2*)(g_v + vbase + Dm);

    float s00 = q0.x * k0.x + q0.y * k0.y;
    float s01 = q0.x * k1.x + q0.y * k1.y;
    float s10 = q1.x * k0.x + q1.y * k0.y;
    float s11 = q1.x * k1.x + q1.y * k1.y;
#pragma unroll
    for (int o = 16; o; o >>= 1) {
        s00 += __shfl_xor_sync(0xffffffffu, s00, o);
        s01 += __shfl_xor_sync(0xffffffffu, s01, o);
        s10 += __shfl_xor_sync(0xffffffffu, s10, o);
        s11 += __shfl_xor_sync(0xffffffffu, s11, o);
    }
    const float sc = 0.125f;
    s00 *= sc; s01 *= sc; s10 *= sc; s11 *= sc;

    float m0 = fmaxf(s00, s01), m1 = fmaxf(s10, s11);
    float e00 = __expf(s00 - m0), e01 = __expf(s01 - m0);
    float e10 = __expf(s10 - m1), e11 = __expf(s11 - m1);
    float r0 = 1.f / (e00 + e01), r1 = 1.f / (e10 + e11);
    float a00 = e00 * r0, a01 = e01 * r0;
    float a10 = e10 * r1, a11 = e11 * r1;

    float2 o0, o1;
    o0.x = a00 * v0.x + a01 * v1.x;  o0.y = a00 * v0.y + a01 * v1.y;
    o1.x = a10 * v0.x + a11 * v1.x;  o1.y = a10 * v0.y + a11 * v1.y;
    *(float2*)(g_tmp1 + vbase)      = o0;
    *(float2*)(g_tmp1 + vbase + Dm) = o1;
}

// ---------------------------------------------------------------------------
// Block reduction (256 threads)
// ---------------------------------------------------------------------------
__device__ __forceinline__ float block_sum(float v)
{
    __shared__ float red[8];
    __shared__ float total;
    int lane = threadIdx.x & 31, w = threadIdx.x >> 5;
#pragma unroll
    for (int o = 16; o; o >>= 1) v += __shfl_xor_sync(0xffffffffu, v, o);
    __syncthreads();
    if (lane == 0) red[w] = v;
    __syncthreads();
    if (threadIdx.x == 0) {
        float s = 0.f;
#pragma unroll
        for (int i = 0; i < 8; i++) s += red[i];
        total = s;
    }
    __syncthreads();
    return total;
}

__global__ void add_inorm(float* __restrict__ x, const float* __restrict__ delta)
{
    int row = blockIdx.x;
    int tid = threadIdx.x;
    size_t base = (size_t)row * Dm;
    float vals[3];
    float s = 0.f;
#pragma unroll
    for (int i = 0; i < 3; i++) {
        int cidx = tid + i * 256;
        vals[i] = x[base + cidx] + delta[base + cidx];
        s += vals[i];
    }
    float mean = block_sum(s) * (1.f / 768.f);
    float vs = 0.f;
#pragma unroll
    for (int i = 0; i < 3; i++) {
        float d = vals[i] - mean;
        vs += d * d;
    }
    float var = block_sum(vs) * (1.f / 768.f);
    float rs = rsqrtf(var + EPSf);
#pragma unroll
    for (int i = 0; i < 3; i++)
        x[base + tid + i * 256] = (vals[i] - mean) * rs;
}

__global__ void final_out(float* __restrict__ out)
{
    int n = blockIdx.x;
    int tid = threadIdx.x;
    size_t base = (size_t)(2 * n) * Dm;
    float vals[3];
    float s = 0.f;
#pragma unroll
    for (int i = 0; i < 3; i++) {
        int cidx = tid + i * 256;
        vals[i] = g_x[base + cidx] + g_x[base + Dm + cidx];
        s += vals[i];
    }
    float mean = block_sum(s) * (1.f / 768.f);
    float vs = 0.f;
#pragma unroll
    for (int i = 0; i < 3; i++) {
        float d = vals[i] - mean;
        vs += d * d;
    }
    float var = block_sum(vs) * (1.f / 768.f);
    float rs = rsqrtf(var + EPSf);
#pragma unroll
    for (int i = 0; i < 3; i++)
        out[(size_t)n * Dm + tid + i * 256] = (vals[i] - mean) * rs;
}

__global__ void dot_scores(const float* __restrict__ pc,
                           const float* __restrict__ lc,
                           const float* __restrict__ rc,
                           float* __restrict__ out)
{
    int gw   = (blockIdx.x * blockDim.x + threadIdx.x) >> 5;
    int lane = threadIdx.x & 31;
    if (gw >= NSEQ) return;
    int i     = gw >> 1;
    int which = gw & 1;
    int b     = i >> 5;
    const float* u = pc + b * CSm;
    const float* w = (which == 0 ? rc : lc) + (size_t)i * CSm;
    float s = 0.f;
#pragma unroll 4
    for (int j = lane; j < CSm; j += 32) s += u[j] * w[j];
#pragma unroll
    for (int o = 16; o; o >>= 1) s += __shfl_xor_sync(0xffffffffu, s, o);
    if (lane == 0) out[gw] = s * 0.044194173824159216f;
}

// ---------------------------------------------------------------------------
// Host launcher
// ---------------------------------------------------------------------------
static float* devptr(const void* sym)
{
    void* p = nullptr;
    cudaGetSymbolAddress(&p, sym);
    return (float*)p;
}

extern "C" void kernel_launch(void* const* d_in, const int* in_sizes, int n_in,
                              void* d_out, int out_size)
{
    (void)in_sizes; (void)n_in; (void)out_size;

    const float* parent     = (const float*)d_in[0];
    const float* child      = (const float*)d_in[1];
    const float* attn_in_w  = (const float*)d_in[4];
    const float* attn_in_b  = (const float*)d_in[5];
    const float* attn_out_w = (const float*)d_in[6];
    const float* attn_out_b = (const float*)d_in[7];
    const float* lin1_w     = (const float*)d_in[8];
    const float* lin1_b     = (const float*)d_in[9];
    const float* lin2_w     = (const float*)d_in[10];
    const float* lin2_b     = (const float*)d_in[11];
    const float* pos_emb    = (const float*)d_in[12];
    const float* parent_w1  = (const float*)d_in[13];
    const float* parent_b1  = (const float*)d_in[14];
    const float* parent_w2  = (const float*)d_in[15];
    const float* parent_b2  = (const float*)d_in[16];
    const float* left_w1    = (const float*)d_in[17];
    const float* left_b1    = (const float*)d_in[18];
    const float* left_w2    = (const float*)d_in[19];
    const float* left_b2    = (const float*)d_in[20];
    const float* right_w1   = (const float*)d_in[21];
    const float* right_b1   = (const float*)d_in[22];
    const float* right_w2   = (const float*)d_in[23];
    const float* right_b2   = (const float*)d_in[24];
    float* out = (float*)d_out;

    float* px   = devptr(g_x);
    float* ptmp = devptr(g_tmp1);
    float* pqk  = devptr(g_qk);
    float* pv   = devptr(g_v);
    float* pt   = devptr(g_t);
    float* phid = devptr(g_hid);

    const int EW = (TT * Dm) / 256;

    build_x<<<EW, 256>>>(parent, child);

    // ---- outside-score path ----
    {
        dim3 gP (Dm  / 128, Bm / 128);
        dim3 gP2(CSm / 128, Bm / 128);
        dim3 gC (Dm  / 128, 8192 / 128);
        dim3 gC2(CSm / 128, 8192 / 128);
        gemm_tf32<true ><<<gP , 256>>>(parent, Dm, parent_w1, parent_b1, phid,           Dm,  Dm);
        gemm_tf32<false><<<gP2, 256>>>(phid,   Dm, parent_w2, parent_b2, phid + Bm * Dm, CSm, Dm);
        gemm_tf32<true ><<<gC , 256>>>(child,      2 * Dm, left_w1,  left_b1,  ptmp, Dm,  Dm);
        gemm_tf32<false><<<gC2, 256>>>(ptmp,       Dm,     left_w2,  left_b2,  pt,   CSm, Dm);
        gemm_tf32<true ><<<gC , 256>>>(child + Dm, 2 * Dm, right_w1, right_b1, pv,   Dm,  Dm);
        gemm_tf32<false><<<gC2, 256>>>(pv,         Dm,     right_w2, right_b2, pqk,  CSm, Dm);
        dot_scores<<<(NSEQ * 32) / 256, 256>>>(phid + Bm * Dm, pt, pqk, out);
    }

    // ---- 3 tree-transformer layers ----
    dim3 gQK(1536 / 128, TT / 128);
    dim3 gD (Dm   / 128, TT / 128);
    dim3 gM1(FFm  / 128, TT / 128);

    for (int l = 0; l < Lm; l++) {
        const float* iw = attn_in_w  + (size_t)l * 3 * Dm * Dm;
        const float* ib = attn_in_b  + (size_t)l * 3 * Dm;
        const float* ow = attn_out_w + (size_t)l * Dm * Dm;
        const float* ob = attn_out_b + (size_t)l * Dm;
        const float* w1 = lin1_w     + (size_t)l * FFm * Dm;
        const float* b1 = lin1_b     + (size_t)l * FFm;
        const float* w2 = lin2_w     + (size_t)l * Dm * FFm;
        const float* b2 = lin2_b     + (size_t)l * Dm;

        add_pe<<<EW, 256>>>(pos_emb + (size_t)l * 4 * Dm);
        gemm_tf32<false><<<gQK, 256>>>(ptmp, Dm, iw,               ib,          pqk, 2 * Dm, Dm);
        gemm_tf32<false><<<gD , 256>>>(px,   Dm, iw + 2 * Dm * Dm, ib + 2 * Dm, pv,  Dm,     Dm);
        attn2<<<(NSEQ * Hm * 32) / 256, 256>>>();
        gemm_tf32<false><<<gD , 256>>>(ptmp, Dm, ow, ob, pt, Dm, Dm);
        add_inorm<<<TT, 256>>>(px, pt);
        gemm_tf32<true ><<<gM1, 256>>>(px,   Dm,  w1, b1, phid, FFm, Dm);
        gemm_tf32<false><<<gD , 256>>>(phid, FFm, w2, b2, pt,   Dm,  FFm);
        add_inorm<<<TT, 256>>>(px, pt);
    }

    final_out<<<NSEQ, 256>>>(out + NSEQ);
}

// round 3
// speedup vs baseline: 3.1510x; 1.0995x over previous
#include <cuda_runtime.h>
#include <math.h>
#include <stdint.h>

// ---------------------------------------------------------------------------
// Problem constants
// ---------------------------------------------------------------------------
namespace {
constexpr int Dm   = 768;
constexpr int FFm  = 3072;
constexpr int Hm   = 12;
constexpr int Lm   = 3;
constexpr int CSm  = 512;
constexpr int Bm   = 256;
constexpr int NSEQ = 16384;         // B*C*2 sequences of 2 tokens
constexpr int TT   = NSEQ * 2;      // 32768 tokens
constexpr float EPSf = 1e-5f;
}

// ---------------------------------------------------------------------------
// Scratch (device globals; no runtime allocation allowed)
// ---------------------------------------------------------------------------
__device__ float g_x   [TT * Dm];        // fp32 token state (residual path)
__device__ float g_xt  [TT * Dm];        // tf32-rounded copy of g_x (GEMM A)
__device__ float g_tmp1[TT * Dm];        // qk_in / attn-out (tf32-rounded)
__device__ float g_qk  [TT * 2 * Dm];
__device__ float g_v   [TT * Dm];
__device__ float g_t   [TT * Dm];
__device__ float g_hid [TT * FFm];
__device__ float g_wt  [24182784];       // tf32-rounded weights (all layers)
__device__ float g_ct  [TT * Dm];        // tf32-rounded child
__device__ float g_pt  [Bm * Dm];        // tf32-rounded parent

__device__ __forceinline__ float gelu_f(float x) {
    return 0.5f * x * (1.0f + erff(x * 0.7071067811865475f));
}

__device__ __forceinline__ float to_tf32(float x) {
    uint32_t u;
    asm("cvt.rna.tf32.f32 %0, %1;" : "=r"(u) : "f"(x));
    return __uint_as_float(u);
}

__device__ __forceinline__ void cp_async16(uint32_t s, const float* g) {
    asm volatile("cp.async.cg.shared.global [%0], [%1], 16;\n" :: "r"(s), "l"(g));
}
__device__ __forceinline__ void cp_commit() {
    asm volatile("cp.async.commit_group;\n");
}
template <int N> __device__ __forceinline__ void cp_wait() {
    asm volatile("cp.async.wait_group %0;\n" :: "n"(N));
}

// ---------------------------------------------------------------------------
// tf32 tensor-core NT GEMM:  C[M,N] = A[M,K] @ B[N,K]^T + bias[N]
// A,B already tf32-rounded fp32 bit patterns in GMEM.
// BM=BN=128, BK=16, 256 threads (8 warps 4x2), warp tile 32x64,
// mma.sync.m16n8k8.tf32. 4-stage cp.async pipeline, padded SMEM (stride 20).
// All M,N multiples of 128, K multiples of 16, K>=48*16 handled generally.
// ---------------------------------------------------------------------------
template <bool GELU, bool ROUND>
__global__ void __launch_bounds__(256, 2) gemm_tc(
    const float* __restrict__ A, int lda,
    const float* __restrict__ B,              // [N,K] row-major (ldb == K)
    const float* __restrict__ bias,
    float* __restrict__ C, int ldc, int K)
{
    constexpr int BM = 128, BN = 128, BK = 16, LDs = 20, ST = 4;
    constexpr int TILE = BM * LDs;             // floats per stage tile
    extern __shared__ float sm[];
    float* As = sm;                            // ST * TILE
    float* Bs = sm + ST * TILE;                // ST * TILE

    const int tid  = threadIdx.x;
    const int bm   = blockIdx.y * BM;
    const int bn   = blockIdx.x * BN;
    const int lane = tid & 31;
    const int wid  = tid >> 5;
    const int wm   = wid & 3;
    const int wn   = wid >> 2;
    const int g    = lane >> 2;
    const int tg   = lane & 3;

    const int lrow = tid >> 2;                 // 0..63
    const int lc   = (tid & 3) << 2;           // 0,4,8,12
    const float* Ap = A + (size_t)(bm + lrow) * lda + lc;
    const float* Bp = B + (size_t)(bn + lrow) * K   + lc;

    uint32_t sA = (uint32_t)__cvta_generic_to_shared(As) + (lrow * LDs + lc) * 4u;
    uint32_t sB = (uint32_t)__cvta_generic_to_shared(Bs) + (lrow * LDs + lc) * 4u;

    const int nk = K / BK;

    auto issue = [&](int stage, int kof) {
        uint32_t a = sA + stage * (TILE * 4);
        uint32_t b = sB + stage * (TILE * 4);
        cp_async16(a,                 Ap + kof);
        cp_async16(a + 64 * LDs * 4,  Ap + kof + (size_t)64 * lda);
        cp_async16(b,                 Bp + kof);
        cp_async16(b + 64 * LDs * 4,  Bp + kof + (size_t)64 * K);
        cp_commit();
    };

    float c[2][8][4];
#pragma unroll
    for (int mt = 0; mt < 2; mt++)
#pragma unroll
        for (int nt = 0; nt < 8; nt++)
#pragma unroll
            for (int j = 0; j < 4; j++) c[mt][nt][j] = 0.f;

    issue(0, 0);
    issue(1, BK);
    issue(2, 2 * BK);

    for (int it = 0; it < nk; it++) {
        cp_wait<2>();
        __syncthreads();

        if (it + 3 < nk) issue((it + 3) & 3, (it + 3) * BK);
        else             cp_commit();          // keep wait_group arithmetic exact

        const float* as = As + (it & 3) * TILE;
        const float* bs = Bs + (it & 3) * TILE;
#pragma unroll
        for (int ks = 0; ks < 2; ks++) {
            const int k1 = ks * 8 + tg;
            uint32_t a[2][4], b[8][2];
#pragma unroll
            for (int mt = 0; mt < 2; mt++) {
                const int r = (wm * 32 + mt * 16 + g) * LDs;
                a[mt][0] = __float_as_uint(as[r + k1]);
                a[mt][1] = __float_as_uint(as[r + 8 * LDs + k1]);
                a[mt][2] = __float_as_uint(as[r + k1 + 4]);
                a[mt][3] = __float_as_uint(as[r + 8 * LDs + k1 + 4]);
            }
#pragma unroll
            for (int nt = 0; nt < 8; nt++) {
                const int r = (wn * 64 + nt * 8 + g) * LDs;
                b[nt][0] = __float_as_uint(bs[r + k1]);
                b[nt][1] = __float_as_uint(bs[r + k1 + 4]);
            }
#pragma unroll
            for (int mt = 0; mt < 2; mt++)
#pragma unroll
                for (int nt = 0; nt < 8; nt++) {
                    asm volatile(
                        "mma.sync.aligned.m16n8k8.row.col.f32.tf32.tf32.f32 "
                        "{%0,%1,%2,%3}, {%4,%5,%6,%7}, {%8,%9}, {%0,%1,%2,%3};"
                        : "+f"(c[mt][nt][0]), "+f"(c[mt][nt][1]),
                          "+f"(c[mt][nt][2]), "+f"(c[mt][nt][3])
                        : "r"(a[mt][0]), "r"(a[mt][1]), "r"(a[mt][2]), "r"(a[mt][3]),
                          "r"(b[nt][0]), "r"(b[nt][1]));
                }
        }
        __syncthreads();
    }

    // Epilogue: bias (+ optional exact GELU, optional tf32 rounding)
#pragma unroll
    for (int mt = 0; mt < 2; mt++) {
        const int row = bm + wm * 32 + mt * 16 + g;
#pragma unroll
        for (int nt = 0; nt < 8; nt++) {
            const int col = bn + wn * 64 + nt * 8 + 2 * tg;
            const float bx = bias[col], by = bias[col + 1];
            float2 v0, v1;
            v0.x = c[mt][nt][0] + bx;  v0.y = c[mt][nt][1] + by;
            v1.x = c[mt][nt][2] + bx;  v1.y = c[mt][nt][3] + by;
            if (GELU) {
                v0.x = gelu_f(v0.x); v0.y = gelu_f(v0.y);
                v1.x = gelu_f(v1.x); v1.y = gelu_f(v1.y);
            }
            if (ROUND) {
                v0.x = to_tf32(v0.x); v0.y = to_tf32(v0.y);
                v1.x = to_tf32(v1.x); v1.y = to_tf32(v1.y);
            }
            *(float2*)(C + (size_t)row * ldc + col)       = v0;
            *(float2*)(C + (size_t)(row + 8) * ldc + col) = v1;
        }
    }
}

// ---------------------------------------------------------------------------
// tf32 rounding copy (vectorized)
// ---------------------------------------------------------------------------
__global__ void round_copy(const float4* __restrict__ in,
                           float4* __restrict__ out, int n4)
{
    int i = blockIdx.x * blockDim.x + threadIdx.x;
    if (i >= n4) return;
    float4 v = in[i];
    v.x = to_tf32(v.x); v.y = to_tf32(v.y);
    v.z = to_tf32(v.z); v.w = to_tf32(v.w);
    out[i] = v;
}

// ---------------------------------------------------------------------------
// x construction: token 2n = parent[b], token 2n+1 = child[n^1]
// writes fp32 state + tf32-rounded copy
// ---------------------------------------------------------------------------
__global__ void build_x(const float* __restrict__ parent,
                        const float* __restrict__ child)
{
    int idx = blockIdx.x * blockDim.x + threadIdx.x;
    if (idx >= TT * Dm) return;
    int t = idx / Dm;
    int d = idx - t * Dm;
    int n = t >> 1;
    float val;
    if ((t & 1) == 0) {
        int b = n >> 6;
        val = parent[b * Dm + d];
    } else {
        val = child[(size_t)(n ^ 1) * Dm + d];
    }
    g_x[idx]  = val;
    g_xt[idx] = to_tf32(val);
}

// qk_in = x + pe (tf32-rounded; GEMM-input only)
__global__ void add_pe(const float* __restrict__ pe_l)
{
    int idx = blockIdx.x * blockDim.x + threadIdx.x;
    if (idx >= TT * Dm) return;
    int t = idx / Dm;
    int d = idx - t * Dm;
    int role = (t & 1) ? (1 + ((t >> 1) & 1)) : 0;
    g_tmp1[idx] = to_tf32(g_x[idx] + pe_l[role * Dm + d]);
}

// ---------------------------------------------------------------------------
// 2x2 attention per (sequence, head). One warp per (n,h).
// Output tf32-rounded (feeds out-proj GEMM only).
// ---------------------------------------------------------------------------
__global__ void attn2()
{
    int gw   = (blockIdx.x * blockDim.x + threadIdx.x) >> 5;
    int lane = threadIdx.x & 31;
    if (gw >= NSEQ * Hm) return;
    int n = gw / Hm;
    int h = gw - n * Hm;

    size_t qbase = (size_t)(2 * n) * (2 * Dm) + h * 64 + 2 * lane;
    float2 q0 = *(const float2*)(g_qk + qbase);
    float2 k0 = *(const float2*)(g_qk + qbase + Dm);
    float2 q1 = *(const float2*)(g_qk + qbase + 2 * Dm);
    float2 k1 = *(const float2*)(g_qk + qbase + 3 * Dm);

    size_t vbase = (size_t)(2 * n) * Dm + h * 64 + 2 * lane;
    float2 v0 = *(const float2*)(g_v + vbase);
    float2 v1 = *(const float2*)(g_v + vbase + Dm);

    float s00 = q0.x * k0.x + q0.y * k0.y;
    float s01 = q0.x * k1.x + q0.y * k1.y;
    float s10 = q1.x * k0.x + q1.y * k0.y;
    float s11 = q1.x * k1.x + q1.y * k1.y;
#pragma unroll
    for (int o = 16; o; o >>= 1) {
        s00 += __shfl_xor_sync(0xffffffffu, s00, o);
        s01 += __shfl_xor_sync(0xffffffffu, s01, o);
        s10 += __shfl_xor_sync(0xffffffffu, s10, o);
        s11 += __shfl_xor_sync(0xffffffffu, s11, o);
    }
    const float sc = 0.125f;
    s00 *= sc; s01 *= sc; s10 *= sc; s11 *= sc;

    float m0 = fmaxf(s00, s01), m1 = fmaxf(s10, s11);
    float e00 = __expf(s00 - m0), e01 = __expf(s01 - m0);
    float e10 = __expf(s10 - m1), e11 = __expf(s11 - m1);
    float r0 = 1.f / (e00 + e01), r1 = 1.f / (e10 + e11);
    float a00 = e00 * r0, a01 = e01 * r0;
    float a10 = e10 * r1, a11 = e11 * r1;

    float2 o0, o1;
    o0.x = to_tf32(a00 * v0.x + a01 * v1.x);
    o0.y = to_tf32(a00 * v0.y + a01 * v1.y);
    o1.x = to_tf32(a10 * v0.x + a11 * v1.x);
    o1.y = to_tf32(a10 * v0.y + a11 * v1.y);
    *(float2*)(g_tmp1 + vbase)      = o0;
    *(float2*)(g_tmp1 + vbase + Dm) = o1;
}

// ---------------------------------------------------------------------------
// Block reduction (256 threads)
// ---------------------------------------------------------------------------
__device__ __forceinline__ float block_sum(float v)
{
    __shared__ float red[8];
    __shared__ float total;
    int lane = threadIdx.x & 31, w = threadIdx.x >> 5;
#pragma unroll
    for (int o = 16; o; o >>= 1) v += __shfl_xor_sync(0xffffffffu, v, o);
    __syncthreads();
    if (lane == 0) red[w] = v;
    __syncthreads();
    if (threadIdx.x == 0) {
        float s = 0.f;
#pragma unroll
        for (int i = 0; i < 8; i++) s += red[i];
        total = s;
    }
    __syncthreads();
    return total;
}

// x = inorm(x + delta): writes fp32 + tf32 copies
__global__ void add_inorm(float* __restrict__ x, float* __restrict__ xt,
                          const float* __restrict__ delta)
{
    int row = blockIdx.x;
    int tid = threadIdx.x;
    size_t base = (size_t)row * Dm;
    float vals[3];
    float s = 0.f;
#pragma unroll
    for (int i = 0; i < 3; i++) {
        int cidx = tid + i * 256;
        vals[i] = x[base + cidx] + delta[base + cidx];
        s += vals[i];
    }
    float mean = block_sum(s) * (1.f / 768.f);
    float vs = 0.f;
#pragma unroll
    for (int i = 0; i < 3; i++) {
        float d = vals[i] - mean;
        vs += d * d;
    }
    float var = block_sum(vs) * (1.f / 768.f);
    float rs = rsqrtf(var + EPSf);
#pragma unroll
    for (int i = 0; i < 3; i++) {
        float r = (vals[i] - mean) * rs;
        x [base + tid + i * 256] = r;
        xt[base + tid + i * 256] = to_tf32(r);
    }
}

__global__ void final_out(float* __restrict__ out)
{
    int n = blockIdx.x;
    int tid = threadIdx.x;
    size_t base = (size_t)(2 * n) * Dm;
    float vals[3];
    float s = 0.f;
#pragma unroll
    for (int i = 0; i < 3; i++) {
        int cidx = tid + i * 256;
        vals[i] = g_x[base + cidx] + g_x[base + Dm + cidx];
        s += vals[i];
    }
    float mean = block_sum(s) * (1.f / 768.f);
    float vs = 0.f;
#pragma unroll
    for (int i = 0; i < 3; i++) {
        float d = vals[i] - mean;
        vs += d * d;
    }
    float var = block_sum(vs) * (1.f / 768.f);
    float rs = rsqrtf(var + EPSf);
#pragma unroll
    for (int i = 0; i < 3; i++)
        out[(size_t)n * Dm + tid + i * 256] = (vals[i] - mean) * rs;
}

__global__ void dot_scores(const float* __restrict__ pc,
                           const float* __restrict__ lc,
                           const float* __restrict__ rc,
                           float* __restrict__ out)
{
    int gw   = (blockIdx.x * blockDim.x + threadIdx.x) >> 5;
    int lane = threadIdx.x & 31;
    if (gw >= NSEQ) return;
    int i     = gw >> 1;
    int which = gw & 1;
    int b     = i >> 5;
    const float* u = pc + b * CSm;
    const float* w = (which == 0 ? rc : lc) + (size_t)i * CSm;
    float s = 0.f;
#pragma unroll 4
    for (int j = lane; j < CSm; j += 32) s += u[j] * w[j];
#pragma unroll
    for (int o = 16; o; o >>= 1) s += __shfl_xor_sync(0xffffffffu, s, o);
    if (lane == 0) out[gw] = s * 0.044194173824159216f;
}

// ---------------------------------------------------------------------------
// Host launcher
// ---------------------------------------------------------------------------
static float* devptr(const void* sym)
{
    void* p = nullptr;
    cudaGetSymbolAddress(&p, sym);
    return (float*)p;
}

extern "C" void kernel_launch(void* const* d_in, const int* in_sizes, int n_in,
                              void* d_out, int out_size)
{
    (void)in_sizes; (void)n_in; (void)out_size;

    const float* parent     = (const float*)d_in[0];
    const float* child      = (const float*)d_in[1];
    const float* attn_in_w  = (const float*)d_in[4];
    const float* attn_in_b  = (const float*)d_in[5];
    const float* attn_out_w = (const float*)d_in[6];
    const float* attn_out_b = (const float*)d_in[7];
    const float* lin1_w     = (const float*)d_in[8];
    const float* lin1_b     = (const float*)d_in[9];
    const float* lin2_w     = (const float*)d_in[10];
    const float* lin2_b     = (const float*)d_in[11];
    const float* pos_emb    = (const float*)d_in[12];
    const float* parent_w1  = (const float*)d_in[13];
    const float* parent_b1  = (const float*)d_in[14];
    const float* parent_w2  = (const float*)d_in[15];
    const float* parent_b2  = (const float*)d_in[16];
    const float* left_w1    = (const float*)d_in[17];
    const float* left_b1    = (const float*)d_in[18];
    const float* left_w2    = (const float*)d_in[19];
    const float* left_b2    = (const float*)d_in[20];
    const float* right_w1   = (const float*)d_in[21];
    const float* right_b1   = (const float*)d_in[22];
    const float* right_w2   = (const float*)d_in[23];
    const float* right_b2   = (const float*)d_in[24];
    float* out = (float*)d_out;

    float* px   = devptr(g_x);
    float* pxt  = devptr(g_xt);
    float* ptmp = devptr(g_tmp1);
    float* pqk  = devptr(g_qk);
    float* pv   = devptr(g_v);
    float* pt   = devptr(g_t);
    float* phid = devptr(g_hid);
    float* pwt  = devptr(g_wt);
    float* pct  = devptr(g_ct);
    float* ppt  = devptr(g_pt);

    // dynamic SMEM for the GEMM (80 KB)
    constexpr int SMEMB = 4 * 2 * 128 * 20 * 4;
    static int attr_done = 0;
    if (!attr_done) {
        cudaFuncSetAttribute(gemm_tc<false, false>,
                             cudaFuncAttributeMaxDynamicSharedMemorySize, SMEMB);
        cudaFuncSetAttribute(gemm_tc<true, true>,
                             cudaFuncAttributeMaxDynamicSharedMemorySize, SMEMB);
        attr_done = 1;
    }

    // ---- weight / input tf32 rounding (offsets into g_wt) ----
    struct CV { const float* src; float* dst; int n; };
    const int n_aiw = Lm * 3 * Dm * Dm;   // 5,308,416
    const int n_aow = Lm * Dm * Dm;       // 1,769,472
    const int n_l1  = Lm * FFm * Dm;      // 7,077,888
    const int n_l2  = Lm * Dm * FFm;      // 7,077,888
    const int n_w1  = Dm * Dm;            //   589,824
    const int n_w2  = CSm * Dm;           //   393,216

    float* w_aiw = pwt;
    float* w_aow = w_aiw + n_aiw;
    float* w_l1  = w_aow + n_aow;
    float* w_l2  = w_l1  + n_l1;
    float* w_pw1 = w_l2  + n_l2;
    float* w_pw2 = w_pw1 + n_w1;
    float* w_lw1 = w_pw2 + n_w2;
    float* w_lw2 = w_lw1 + n_w1;
    float* w_rw1 = w_lw2 + n_w2;
    float* w_rw2 = w_rw1 + n_w1;

    CV cvs[] = {
        {attn_in_w,  w_aiw, n_aiw}, {attn_out_w, w_aow, n_aow},
        {lin1_w,     w_l1,  n_l1},  {lin2_w,     w_l2,  n_l2},
        {parent_w1,  w_pw1, n_w1},  {parent_w2,  w_pw2, n_w2},
        {left_w1,    w_lw1, n_w1},  {left_w2,    w_lw2, n_w2},
        {right_w1,   w_rw1, n_w1},  {right_w2,   w_rw2, n_w2},
        {child,      pct,   TT * Dm}, {parent,   ppt,   Bm * Dm},
    };
    for (auto& c : cvs) {
        int n4 = c.n / 4;
        round_copy<<<(n4 + 255) / 256, 256>>>(
            (const float4*)c.src, (float4*)c.dst, n4);
    }

    const int EW = (TT * Dm) / 256;
    build_x<<<EW, 256>>>(parent, child);

    // ---- outside-score path ----
    {
        dim3 gP (Dm  / 128, Bm / 128);
        dim3 gP2(CSm / 128, Bm / 128);
        dim3 gC (Dm  / 128, 8192 / 128);
        dim3 gC2(CSm / 128, 8192 / 128);
        gemm_tc<true , true ><<<gP , 256, SMEMB>>>(ppt, Dm, w_pw1, parent_b1, phid,           Dm,  Dm);
        gemm_tc<false, false><<<gP2, 256, SMEMB>>>(phid, Dm, w_pw2, parent_b2, phid + Bm * Dm, CSm, Dm);
        gemm_tc<true , true ><<<gC , 256, SMEMB>>>(pct,      2 * Dm, w_lw1, left_b1,  ptmp, Dm,  Dm);
        gemm_tc<false, false><<<gC2, 256, SMEMB>>>(ptmp,     Dm,     w_lw2, left_b2,  pt,   CSm, Dm);
        gemm_tc<true , true ><<<gC , 256, SMEMB>>>(pct + Dm, 2 * Dm, w_rw1, right_b1, pv,   Dm,  Dm);
        gemm_tc<false, false><<<gC2, 256, SMEMB>>>(pv,       Dm,     w_rw2, right_b2, pqk,  CSm, Dm);
        dot_scores<<<(NSEQ * 32) / 256, 256>>>(phid + Bm * Dm, pt, pqk, out);
    }

    // ---- 3 tree-transformer layers ----
    dim3 gQK(1536 / 128, TT / 128);
    dim3 gD (Dm   / 128, TT / 128);
    dim3 gM1(FFm  / 128, TT / 128);

    for (int l = 0; l < Lm; l++) {
        const float* iw = w_aiw + (size_t)l * 3 * Dm * Dm;
        const float* ib = attn_in_b  + (size_t)l * 3 * Dm;
        const float* ow = w_aow + (size_t)l * Dm * Dm;
        const float* ob = attn_out_b + (size_t)l * Dm;
        const float* w1 = w_l1  + (size_t)l * FFm * Dm;
        const float* b1 = lin1_b     + (size_t)l * FFm;
        const float* w2 = w_l2  + (size_t)l * Dm * FFm;
        const float* b2 = lin2_b     + (size_t)l * Dm;

        add_pe<<<EW, 256>>>(pos_emb + (size_t)l * 4 * Dm);
        gemm_tc<false, false><<<gQK, 256, SMEMB>>>(ptmp, Dm, iw,               ib,          pqk, 2 * Dm, Dm);
        gemm_tc<false, false><<<gD , 256, SMEMB>>>(pxt,  Dm, iw + 2 * Dm * Dm, ib + 2 * Dm, pv,  Dm,     Dm);
        attn2<<<(NSEQ * Hm * 32) / 256, 256>>>();
        gemm_tc<false, false><<<gD , 256, SMEMB>>>(ptmp, Dm, ow, ob, pt, Dm, Dm);
        add_inorm<<<TT, 256>>>(px, pxt, pt);
        gemm_tc<true , true ><<<gM1, 256, SMEMB>>>(pxt,  Dm,  w1, b1, phid, FFm, Dm);
        gemm_tc<false, false><<<gD , 256, SMEMB>>>(phid, FFm, w2, b2, pt,   Dm,  FFm);
        add_inorm<<<TT, 256>>>(px, pxt, pt);
    }

    final_out<<<NSEQ, 256>>>(out + NSEQ);
}

// round 4
// speedup vs baseline: 5.2816x; 1.6762x over previous
#include <cuda_runtime.h>
#include <cuda_fp16.h>
#include <math.h>
#include <stdint.h>

// ---------------------------------------------------------------------------
// Problem constants
// ---------------------------------------------------------------------------
namespace {
constexpr int Dm   = 768;
constexpr int FFm  = 3072;
constexpr int Hm   = 12;
constexpr int Lm   = 3;
constexpr int CSm  = 512;
constexpr int Bm   = 256;
constexpr int NSEQ = 16384;         // sequences of 2 tokens
constexpr int TT   = NSEQ * 2;      // 32768 tokens
constexpr float EPSf = 1e-5f;
constexpr int PS   = 40;            // smem row stride in halves (80 B)
}

// ---------------------------------------------------------------------------
// Scratch (device globals; no runtime allocation allowed)
// ---------------------------------------------------------------------------
__device__ float g_x [TT * Dm];                  // fp32 residual state
__device__ float g_qk[TT * 2 * Dm];              // QK proj (fp32)
__device__ float g_v [TT * Dm];                  // V proj (fp32)
__device__ float g_t [TT * Dm];                  // GEMM fp32 outputs / pc,lc,rc
__device__ __align__(16) __half g_xh  [TT * Dm];   // half copy of x
__device__ __align__(16) __half g_ah  [TT * Dm];   // qk_in / attn-out / score hiddens
__device__ __align__(16) __half g_hidh[TT * FFm];  // MLP hidden (half)
__device__ __align__(16) __half g_wh  [24182784];  // all weights, half
__device__ __align__(16) __half g_ch  [TT * Dm];   // child, half
__device__ __align__(16) __half g_ph  [Bm * Dm];   // parent, half

__device__ __forceinline__ float gelu_f(float x) {
    return 0.5f * x * (1.0f + erff(x * 0.7071067811865475f));
}

__device__ __forceinline__ void cp_async16(uint32_t s, const void* g) {
    asm volatile("cp.async.cg.shared.global [%0], [%1], 16;\n" :: "r"(s), "l"(g));
}
__device__ __forceinline__ void cp_commit() {
    asm volatile("cp.async.commit_group;\n");
}
template <int N> __device__ __forceinline__ void cp_wait() {
    asm volatile("cp.async.wait_group %0;\n" :: "n"(N));
}
__device__ __forceinline__ void ldsm4(uint32_t& r0, uint32_t& r1,
                                      uint32_t& r2, uint32_t& r3, uint32_t addr) {
    asm volatile("ldmatrix.sync.aligned.m8n8.x4.shared.b16 {%0,%1,%2,%3}, [%4];"
                 : "=r"(r0), "=r"(r1), "=r"(r2), "=r"(r3) : "r"(addr));
}
__device__ __forceinline__ void mma16816(float* c, const uint32_t* a, const uint32_t* b) {
    asm volatile(
        "mma.sync.aligned.m16n8k16.row.col.f32.f16.f16.f32 "
        "{%0,%1,%2,%3}, {%4,%5,%6,%7}, {%8,%9}, {%0,%1,%2,%3};"
        : "+f"(c[0]), "+f"(c[1]), "+f"(c[2]), "+f"(c[3])
        : "r"(a[0]), "r"(a[1]), "r"(a[2]), "r"(a[3]), "r"(b[0]), "r"(b[1]));
}

// ---------------------------------------------------------------------------
// fp16 tensor-core NT GEMM: C[M,N] = A[M,K] @ B[N,K]^T + bias[N]
// CTA tile 128x256, 8 warps (2m x 4n), warp tile 64x64, BK=32,
// m16n8k16 HMMA + ldmatrix.x4 fragments, 4-stage cp.async pipeline.
// M % 128 == 0, N % 256 == 0, K % 32 == 0 (all true in this problem).
// ---------------------------------------------------------------------------
template <bool GELU, bool HALFOUT>
__global__ void __launch_bounds__(256, 1) hgemm(
    const __half* __restrict__ A, int lda,
    const __half* __restrict__ B,              // [N,K] row-major (ldb == K)
    const float* __restrict__ bias,
    void* __restrict__ Cv, int ldc, int K)
{
    constexpr int BM = 128, BN = 256, BK = 32;
    constexpr int ASZ = BM * PS;               // 5120 halves / stage
    constexpr int BSZ = BN * PS;               // 10240 halves / stage
    extern __shared__ __half sh[];
    __half* As = sh;                           // 4 * ASZ
    __half* Bs = sh + 4 * ASZ;                 // 4 * BSZ

    const int tid  = threadIdx.x;
    const int lane = tid & 31;
    const int wid  = tid >> 5;
    const int wm   = wid >> 2;                 // 0..1
    const int wn   = wid & 3;                  // 0..3
    const int bm   = blockIdx.y * BM;
    const int bn   = blockIdx.x * BN;

    // cp.async staging: each thread copies 16B chunks
    const int arow = tid >> 2;                 // 0..63
    const int acol = (tid & 3) * 8;            // halves: 0,8,16,24
    const __half* Ap = A + (size_t)(bm + arow) * lda + acol;
    const __half* Bp = B + (size_t)(bn + arow) * K   + acol;

    const uint32_t sAbase = (uint32_t)__cvta_generic_to_shared(As);
    const uint32_t sBbase = (uint32_t)__cvta_generic_to_shared(Bs);
    const uint32_t sA = sAbase + (arow * PS + acol) * 2;
    const uint32_t sB = sBbase + (arow * PS + acol) * 2;

    const int nk = K / BK;

    auto issue = [&](int st, int kof) {
        uint32_t a = sA + st * (ASZ * 2);
        uint32_t b = sB + st * (BSZ * 2);
        cp_async16(a,                Ap + kof);
        cp_async16(a + 64 * PS * 2,  Ap + kof + (size_t)64 * lda);
        cp_async16(b,                Bp + kof);
        cp_async16(b + 64 * PS * 2,  Bp + kof + (size_t)64  * K);
        cp_async16(b + 128 * PS * 2, Bp + kof + (size_t)128 * K);
        cp_async16(b + 192 * PS * 2, Bp + kof + (size_t)192 * K);
        cp_commit();
    };

    float c[4][8][4];
#pragma unroll
    for (int mt = 0; mt < 4; mt++)
#pragma unroll
        for (int nt = 0; nt < 8; nt++)
#pragma unroll
            for (int j = 0; j < 4; j++) c[mt][nt][j] = 0.f;

    // ldmatrix lane offsets (in halves, within a stage)
    const int aOff = (wm * 64 + (lane & 15)) * PS + (lane >> 4) * 8;
    const int bOff = (wn * 64 + (lane & 7) + ((lane >> 4) & 1) * 8) * PS
                   + ((lane >> 3) & 1) * 8;

    issue(0, 0);
    issue(1, BK);
    issue(2, 2 * BK);

    for (int it = 0; it < nk; it++) {
        cp_wait<2>();
        __syncthreads();
        if (it + 3 < nk) issue((it + 3) & 3, (it + 3) * BK);
        else             cp_commit();

        const uint32_t aS = sAbase + ((it & 3) * ASZ) * 2;
        const uint32_t bS = sBbase + ((it & 3) * BSZ) * 2;
#pragma unroll
        for (int ks = 0; ks < 2; ks++) {
            uint32_t a[4][4], b[8][2];
#pragma unroll
            for (int mt = 0; mt < 4; mt++)
                ldsm4(a[mt][0], a[mt][1], a[mt][2], a[mt][3],
                      aS + (aOff + mt * 16 * PS + ks * 16) * 2);
#pragma unroll
            for (int np = 0; np < 4; np++)
                ldsm4(b[2 * np][0], b[2 * np][1], b[2 * np + 1][0], b[2 * np + 1][1],
                      bS + (bOff + np * 16 * PS + ks * 16) * 2);
#pragma unroll
            for (int mt = 0; mt < 4; mt++)
#pragma unroll
                for (int nt = 0; nt < 8; nt++)
                    mma16816(c[mt][nt], a[mt], b[nt]);
        }
    }

    // Epilogue: bias (+ optional exact GELU), fp32 or fp16 output
    const int g  = lane >> 2;
    const int tg = lane & 3;
#pragma unroll
    for (int mt = 0; mt < 4; mt++) {
        const int row = bm + wm * 64 + mt * 16 + g;
#pragma unroll
        for (int nt = 0; nt < 8; nt++) {
            const int col = bn + wn * 64 + nt * 8 + 2 * tg;
            const float bx = bias[col], by = bias[col + 1];
            float v0x = c[mt][nt][0] + bx, v0y = c[mt][nt][1] + by;
            float v1x = c[mt][nt][2] + bx, v1y = c[mt][nt][3] + by;
            if (GELU) {
                v0x = gelu_f(v0x); v0y = gelu_f(v0y);
                v1x = gelu_f(v1x); v1y = gelu_f(v1y);
            }
            if (HALFOUT) {
                __half* C = (__half*)Cv;
                *(__half2*)(C + (size_t)row * ldc + col)       = __floats2half2_rn(v0x, v0y);
                *(__half2*)(C + (size_t)(row + 8) * ldc + col) = __floats2half2_rn(v1x, v1y);
            } else {
                float* C = (float*)Cv;
                *(float2*)(C + (size_t)row * ldc + col)       = make_float2(v0x, v0y);
                *(float2*)(C + (size_t)(row + 8) * ldc + col) = make_float2(v1x, v1y);
            }
        }
    }
}

// ---------------------------------------------------------------------------
// fp32 -> fp16 conversion copy
// ---------------------------------------------------------------------------
__global__ void cvt_half(const float2* __restrict__ in,
                         __half2* __restrict__ out, int n2)
{
    int i = blockIdx.x * blockDim.x + threadIdx.x;
    if (i >= n2) return;
    float2 v = in[i];
    out[i] = __floats2half2_rn(v.x, v.y);
}

// ---------------------------------------------------------------------------
// x construction: token 2n = parent[b], token 2n+1 = child[n^1]
// ---------------------------------------------------------------------------
__global__ void build_x(const float* __restrict__ parent,
                        const float* __restrict__ child)
{
    int idx = blockIdx.x * blockDim.x + threadIdx.x;
    if (idx >= TT * Dm) return;
    int t = idx / Dm;
    int d = idx - t * Dm;
    int n = t >> 1;
    float val;
    if ((t & 1) == 0) {
        int b = n >> 6;
        val = parent[b * Dm + d];
    } else {
        val = child[(size_t)(n ^ 1) * Dm + d];
    }
    g_x[idx]  = val;
    g_xh[idx] = __float2half_rn(val);
}

// qk_in = x + pe (half; GEMM input only)
__global__ void add_pe(const float* __restrict__ pe_l)
{
    int idx = blockIdx.x * blockDim.x + threadIdx.x;
    if (idx >= TT * Dm) return;
    int t = idx / Dm;
    int d = idx - t * Dm;
    int role = (t & 1) ? (1 + ((t >> 1) & 1)) : 0;
    g_ah[idx] = __float2half_rn(g_x[idx] + pe_l[role * Dm + d]);
}

// ---------------------------------------------------------------------------
// 2x2 attention per (sequence, head). One warp per (n,h). Output half->g_ah.
// ---------------------------------------------------------------------------
__global__ void attn2()
{
    int gw   = (blockIdx.x * blockDim.x + threadIdx.x) >> 5;
    int lane = threadIdx.x & 31;
    if (gw >= NSEQ * Hm) return;
    int n = gw / Hm;
    int h = gw - n * Hm;

    size_t qbase = (size_t)(2 * n) * (2 * Dm) + h * 64 + 2 * lane;
    float2 q0 = *(const float2*)(g_qk + qbase);
    float2 k0 = *(const float2*)(g_qk + qbase + Dm);
    float2 q1 = *(const float2*)(g_qk + qbase + 2 * Dm);
    float2 k1 = *(const float2*)(g_qk + qbase + 3 * Dm);

    size_t vbase = (size_t)(2 * n) * Dm + h * 64 + 2 * lane;
    float2 v0 = *(const float2*)(g_v + vbase);
    float2 v1 = *(const float2*)(g_v + vbase + Dm);

    float s00 = q0.x * k0.x + q0.y * k0.y;
    float s01 = q0.x * k1.x + q0.y * k1.y;
    float s10 = q1.x * k0.x + q1.y * k0.y;
    float s11 = q1.x * k1.x + q1.y * k1.y;
#pragma unroll
    for (int o = 16; o; o >>= 1) {
        s00 += __shfl_xor_sync(0xffffffffu, s00, o);
        s01 += __shfl_xor_sync(0xffffffffu, s01, o);
        s10 += __shfl_xor_sync(0xffffffffu, s10, o);
        s11 += __shfl_xor_sync(0xffffffffu, s11, o);
    }
    const float sc = 0.125f;
    s00 *= sc; s01 *= sc; s10 *= sc; s11 *= sc;

    float m0 = fmaxf(s00, s01), m1 = fmaxf(s10, s11);
    float e00 = __expf(s00 - m0), e01 = __expf(s01 - m0);
    float e10 = __expf(s10 - m1), e11 = __expf(s11 - m1);
    float r0 = 1.f / (e00 + e01), r1 = 1.f / (e10 + e11);
    float a00 = e00 * r0, a01 = e01 * r0;
    float a10 = e10 * r1, a11 = e11 * r1;

    *(__half2*)(g_ah + vbase) =
        __floats2half2_rn(a00 * v0.x + a01 * v1.x, a00 * v0.y + a01 * v1.y);
    *(__half2*)(g_ah + vbase + Dm) =
        __floats2half2_rn(a10 * v0.x + a11 * v1.x, a10 * v0.y + a11 * v1.y);
}

// ---------------------------------------------------------------------------
// Block reduction (256 threads)
// ---------------------------------------------------------------------------
__device__ __forceinline__ float block_sum(float v)
{
    __shared__ float red[8];
    __shared__ float total;
    int lane = threadIdx.x & 31, w = threadIdx.x >> 5;
#pragma unroll
    for (int o = 16; o; o >>= 1) v += __shfl_xor_sync(0xffffffffu, v, o);
    __syncthreads();
    if (lane == 0) red[w] = v;
    __syncthreads();
    if (threadIdx.x == 0) {
        float s = 0.f;
#pragma unroll
        for (int i = 0; i < 8; i++) s += red[i];
        total = s;
    }
    __syncthreads();
    return total;
}

// x = inorm(x + delta): fp32 state + half copy
__global__ void add_inorm(float* __restrict__ x, __half* __restrict__ xh,
                          const float* __restrict__ delta)
{
    int row = blockIdx.x;
    int tid = threadIdx.x;
    size_t base = (size_t)row * Dm;
    float vals[3];
    float s = 0.f;
#pragma unroll
    for (int i = 0; i < 3; i++) {
        int cidx = tid + i * 256;
        vals[i] = x[base + cidx] + delta[base + cidx];
        s += vals[i];
    }
    float mean = block_sum(s) * (1.f / 768.f);
    float vs = 0.f;
#pragma unroll
    for (int i = 0; i < 3; i++) {
        float d = vals[i] - mean;
        vs += d * d;
    }
    float var = block_sum(vs) * (1.f / 768.f);
    float rs = rsqrtf(var + EPSf);
#pragma unroll
    for (int i = 0; i < 3; i++) {
        float r = (vals[i] - mean) * rs;
        x [base + tid + i * 256] = r;
        xh[base + tid + i * 256] = __float2half_rn(r);
    }
}

__global__ void final_out(float* __restrict__ out)
{
    int n = blockIdx.x;
    int tid = threadIdx.x;
    size_t base = (size_t)(2 * n) * Dm;
    float vals[3];
    float s = 0.f;
#pragma unroll
    for (int i = 0; i < 3; i++) {
        int cidx = tid + i * 256;
        vals[i] = g_x[base + cidx] + g_x[base + Dm + cidx];
        s += vals[i];
    }
    float mean = block_sum(s) * (1.f / 768.f);
    float vs = 0.f;
#pragma unroll
    for (int i = 0; i < 3; i++) {
        float d = vals[i] - mean;
        vs += d * d;
    }
    float var = block_sum(vs) * (1.f / 768.f);
    float rs = rsqrtf(var + EPSf);
#pragma unroll
    for (int i = 0; i < 3; i++)
        out[(size_t)n * Dm + tid + i * 256] = (vals[i] - mean) * rs;
}

__global__ void dot_scores(const float* __restrict__ pc,
                           const float* __restrict__ lc,
                           const float* __restrict__ rc,
                           float* __restrict__ out)
{
    int gw   = (blockIdx.x * blockDim.x + threadIdx.x) >> 5;
    int lane = threadIdx.x & 31;
    if (gw >= NSEQ) return;
    int i     = gw >> 1;
    int which = gw & 1;
    int b     = i >> 5;
    const float* u = pc + b * CSm;
    const float* w = (which == 0 ? rc : lc) + (size_t)i * CSm;
    float s = 0.f;
#pragma unroll 4
    for (int j = lane; j < CSm; j += 32) s += u[j] * w[j];
#pragma unroll
    for (int o = 16; o; o >>= 1) s += __shfl_xor_sync(0xffffffffu, s, o);
    if (lane == 0) out[gw] = s * 0.044194173824159216f;
}

// ---------------------------------------------------------------------------
// Host launcher
// ---------------------------------------------------------------------------
static void* devptr(const void* sym)
{
    void* p = nullptr;
    cudaGetSymbolAddress(&p, sym);
    return p;
}

extern "C" void kernel_launch(void* const* d_in, const int* in_sizes, int n_in,
                              void* d_out, int out_size)
{
    (void)in_sizes; (void)n_in; (void)out_size;

    const float* parent     = (const float*)d_in[0];
    const float* child      = (const float*)d_in[1];
    const float* attn_in_w  = (const float*)d_in[4];
    const float* attn_in_b  = (const float*)d_in[5];
    const float* attn_out_w = (const float*)d_in[6];
    const float* attn_out_b = (const float*)d_in[7];
    const float* lin1_w     = (const float*)d_in[8];
    const float* lin1_b     = (const float*)d_in[9];
    const float* lin2_w     = (const float*)d_in[10];
    const float* lin2_b     = (const float*)d_in[11];
    const float* pos_emb    = (const float*)d_in[12];
    const float* parent_w1  = (const float*)d_in[13];
    const float* parent_b1  = (const float*)d_in[14];
    const float* parent_w2  = (const float*)d_in[15];
    const float* parent_b2  = (const float*)d_in[16];
    const float* left_w1    = (const float*)d_in[17];
    const float* left_b1    = (const float*)d_in[18];
    const float* left_w2    = (const float*)d_in[19];
    const float* left_b2    = (const float*)d_in[20];
    const float* right_w1   = (const float*)d_in[21];
    const float* right_b1   = (const float*)d_in[22];
    const float* right_w2   = (const float*)d_in[23];
    const float* right_b2   = (const float*)d_in[24];
    float* out = (float*)d_out;

    float*  px   = (float*) devptr(g_x);
    float*  pqk  = (float*) devptr(g_qk);
    float*  pv   = (float*) devptr(g_v);
    float*  pt   = (float*) devptr(g_t);
    __half* pxh  = (__half*)devptr(g_xh);
    __half* pah  = (__half*)devptr(g_ah);
    __half* phid = (__half*)devptr(g_hidh);
    __half* pwh  = (__half*)devptr(g_wh);
    __half* pch  = (__half*)devptr(g_ch);
    __half* pph  = (__half*)devptr(g_ph);

    constexpr int SMEMB = (4 * 128 * PS + 4 * 256 * PS) * 2;   // 122880 B
    static int attr_done = 0;
    if (!attr_done) {
        cudaFuncSetAttribute(hgemm<false, false>,
                             cudaFuncAttributeMaxDynamicSharedMemorySize, SMEMB);
        cudaFuncSetAttribute(hgemm<true, true>,
                             cudaFuncAttributeMaxDynamicSharedMemorySize, SMEMB);
        attr_done = 1;
    }

    // ---- weight / input fp16 conversion (offsets into g_wh) ----
    const int n_aiw = Lm * 3 * Dm * Dm;
    const int n_aow = Lm * Dm * Dm;
    const int n_l1  = Lm * FFm * Dm;
    const int n_l2  = Lm * Dm * FFm;
    const int n_w1  = Dm * Dm;
    const int n_w2  = CSm * Dm;

    __half* w_aiw = pwh;
    __half* w_aow = w_aiw + n_aiw;
    __half* w_l1  = w_aow + n_aow;
    __half* w_l2  = w_l1  + n_l1;
    __half* w_pw1 = w_l2  + n_l2;
    __half* w_pw2 = w_pw1 + n_w1;
    __half* w_lw1 = w_pw2 + n_w2;
    __half* w_lw2 = w_lw1 + n_w1;
    __half* w_rw1 = w_lw2 + n_w2;
    __half* w_rw2 = w_rw1 + n_w1;

    struct CV { const float* src; __half* dst; int n; };
    CV cvs[] = {
        {attn_in_w,  w_aiw, n_aiw}, {attn_out_w, w_aow, n_aow},
        {lin1_w,     w_l1,  n_l1},  {lin2_w,     w_l2,  n_l2},
        {parent_w1,  w_pw1, n_w1},  {parent_w2,  w_pw2, n_w2},
        {left_w1,    w_lw1, n_w1},  {left_w2,    w_lw2, n_w2},
        {right_w1,   w_rw1, n_w1},  {right_w2,   w_rw2, n_w2},
        {child,      pch,   NSEQ * Dm}, {parent, pph,   Bm * Dm},
    };
    for (auto& c : cvs) {
        int n2 = c.n / 2;
        cvt_half<<<(n2 + 255) / 256, 256>>>(
            (const float2*)c.src, (__half2*)c.dst, n2);
    }

    const int EW = (TT * Dm) / 256;
    build_x<<<EW, 256>>>(parent, child);

    // ---- outside-score path ----
    {
        // hiddens (half, gelu) packed in g_ah; 512-dim outputs (fp32) in g_t
        __half* h_par = pah;                         // 256 x 768
        __half* h_lft = pah + (size_t)Bm * Dm;       // 8192 x 768
        __half* h_rgt = pah + (size_t)(Bm + 8192) * Dm;
        float*  o_pc  = pt;                          // 256 x 512
        float*  o_lc  = pt + (size_t)Bm * CSm;       // 8192 x 512
        float*  o_rc  = pt + (size_t)(Bm + 8192) * CSm;

        hgemm<true , true ><<<dim3(3, 2),  256, SMEMB>>>(pph,      Dm,     w_pw1, parent_b1, h_par, Dm,  Dm);
        hgemm<false, false><<<dim3(2, 2),  256, SMEMB>>>(h_par,    Dm,     w_pw2, parent_b2, o_pc,  CSm, Dm);
        hgemm<true , true ><<<dim3(3, 64), 256, SMEMB>>>(pch,      2 * Dm, w_lw1, left_b1,   h_lft, Dm,  Dm);
        hgemm<false, false><<<dim3(2, 64), 256, SMEMB>>>(h_lft,    Dm,     w_lw2, left_b2,   o_lc,  CSm, Dm);
        hgemm<true , true ><<<dim3(3, 64), 256, SMEMB>>>(pch + Dm, 2 * Dm, w_rw1, right_b1,  h_rgt, Dm,  Dm);
        hgemm<false, false><<<dim3(2, 64), 256, SMEMB>>>(h_rgt,    Dm,     w_rw2, right_b2,  o_rc,  CSm, Dm);
        dot_scores<<<(NSEQ * 32) / 256, 256>>>(o_pc, o_lc, o_rc, out);
    }

    // ---- 3 tree-transformer layers ----
    dim3 gQK(1536 / 256, TT / 128);
    dim3 gD (Dm   / 256, TT / 128);    // N=768 -> 3
    dim3 gM1(FFm  / 256, TT / 128);

    for (int l = 0; l < Lm; l++) {
        const __half* iw = w_aiw + (size_t)l * 3 * Dm * Dm;
        const float*  ib = attn_in_b  + (size_t)l * 3 * Dm;
        const __half* ow = w_aow + (size_t)l * Dm * Dm;
        const float*  ob = attn_out_b + (size_t)l * Dm;
        const __half* w1 = w_l1  + (size_t)l * FFm * Dm;
        const float*  b1 = lin1_b     + (size_t)l * FFm;
        const __half* w2 = w_l2  + (size_t)l * Dm * FFm;
        const float*  b2 = lin2_b     + (size_t)l * Dm;

        add_pe<<<EW, 256>>>(pos_emb + (size_t)l * 4 * Dm);
        // [Q|K] = (x+pe) @ [Wq;Wk]^T
        hgemm<false, false><<<gQK, 256, SMEMB>>>(pah, Dm, iw,               ib,          pqk, 2 * Dm, Dm);
        // V = x @ Wv^T
        hgemm<false, false><<<gD , 256, SMEMB>>>(pxh, Dm, iw + 2 * Dm * Dm, ib + 2 * Dm, pv,  Dm,     Dm);
        attn2<<<(NSEQ * Hm * 32) / 256, 256>>>();
        // out-proj
        hgemm<false, false><<<gD , 256, SMEMB>>>(pah, Dm, ow, ob, pt, Dm, Dm);
        add_inorm<<<TT, 256>>>(px, pxh, pt);
        // MLP
        hgemm<true , true ><<<gM1, 256, SMEMB>>>(pxh,  Dm,  w1, b1, phid, FFm, Dm);
        hgemm<false, false><<<gD , 256, SMEMB>>>(phid, FFm, w2, b2, pt,   Dm,  FFm);
        add_inorm<<<TT, 256>>>(px, pxh, pt);
    }

    final_out<<<NSEQ, 256>>>(out + NSEQ);
}

// round 6
// speedup vs baseline: 5.5639x; 1.0534x over previous
#include <cuda_runtime.h>
#include <cuda_fp16.h>
#include <math.h>
#include <stdint.h>

// ---------------------------------------------------------------------------
// Problem constants
// ---------------------------------------------------------------------------
namespace {
constexpr int Dm   = 768;
constexpr int FFm  = 3072;
constexpr int Hm   = 12;
constexpr int Lm   = 3;
constexpr int CSm  = 512;
constexpr int Bm   = 256;
constexpr int NSEQ = 16384;         // sequences of 2 tokens
constexpr int TT   = NSEQ * 2;      // 32768 tokens
constexpr float EPSf = 1e-5f;
constexpr int PS   = 40;            // gemm smem row stride in halves (80 B)
constexpr int QKV  = 2304;          // fused QKV width
}

// ---------------------------------------------------------------------------
// Scratch (device globals; no runtime allocation allowed)
// ---------------------------------------------------------------------------
__device__ float g_x [TT * Dm];                    // fp32 residual state
__device__ float g_t [TT * Dm];                    // fp32 GEMM outs / pc,lc,rc
__device__ float g_peq[Lm * 3 * Dm];               // pe @ Wq^T per (layer,role)
__device__ float g_pek[Lm * 3 * Dm];               // pe @ Wk^T per (layer,role)
__device__ __align__(16) __half g_qkvh[TT * QKV];  // fused QKV (half)
__device__ __align__(16) __half g_xh  [TT * Dm];   // half copy of x
__device__ __align__(16) __half g_ah  [TT * Dm];   // attn-out / score hiddens
__device__ __align__(16) __half g_hidh[TT * FFm];  // MLP hidden (half)
__device__ __align__(16) __half g_wh  [24182784];  // all weights, half
__device__ __align__(16) __half g_ch  [TT * Dm];   // child, half
__device__ __align__(16) __half g_ph  [Bm * Dm];   // parent, half

__device__ __forceinline__ float gelu_f(float x) {
    return 0.5f * x * (1.0f + erff(x * 0.7071067811865475f));
}

__device__ __forceinline__ void cp_async16(uint32_t s, const void* g) {
    asm volatile("cp.async.cg.shared.global [%0], [%1], 16;\n" :: "r"(s), "l"(g));
}
__device__ __forceinline__ void cp_commit() {
    asm volatile("cp.async.commit_group;\n");
}
template <int N> __device__ __forceinline__ void cp_wait() {
    asm volatile("cp.async.wait_group %0;\n" :: "n"(N));
}
__device__ __forceinline__ void ldsm4(uint32_t& r0, uint32_t& r1,
                                      uint32_t& r2, uint32_t& r3, uint32_t addr) {
    asm volatile("ldmatrix.sync.aligned.m8n8.x4.shared.b16 {%0,%1,%2,%3}, [%4];"
                 : "=r"(r0), "=r"(r1), "=r"(r2), "=r"(r3) : "r"(addr));
}
__device__ __forceinline__ void mma16816(float* c, const uint32_t* a, const uint32_t* b) {
    asm volatile(
        "mma.sync.aligned.m16n8k16.row.col.f32.f16.f16.f32 "
        "{%0,%1,%2,%3}, {%4,%5,%6,%7}, {%8,%9}, {%0,%1,%2,%3};"
        : "+f"(c[0]), "+f"(c[1]), "+f"(c[2]), "+f"(c[3])
        : "r"(a[0]), "r"(a[1]), "r"(a[2]), "r"(a[3]), "r"(b[0]), "r"(b[1]));
}

// ---------------------------------------------------------------------------
// fp16 tensor-core NT GEMM: C[M,N] = A[M,K] @ B[N,K]^T + bias[N]
// CTA 128x256, 8 warps (2m x 4n), warp tile 64x64, BK=32, m16n8k16 HMMA,
// ldmatrix.x4 fragments, 4-stage cp.async pipeline. (proven in R4)
// ---------------------------------------------------------------------------
template <bool GELU, bool HALFOUT>
__global__ void __launch_bounds__(256, 1) hgemm(
    const __half* __restrict__ A, int lda,
    const __half* __restrict__ B,              // [N,K] row-major (ldb == K)
    const float* __restrict__ bias,
    void* __restrict__ Cv, int ldc, int K)
{
    constexpr int BM = 128, BN = 256, BK = 32;
    constexpr int ASZ = BM * PS;
    constexpr int BSZ = BN * PS;
    extern __shared__ __half sh[];
    __half* As = sh;
    __half* Bs = sh + 4 * ASZ;

    const int tid  = threadIdx.x;
    const int lane = tid & 31;
    const int wid  = tid >> 5;
    const int wm   = wid >> 2;
    const int wn   = wid & 3;
    const int bm   = blockIdx.y * BM;
    const int bn   = blockIdx.x * BN;

    const int arow = tid >> 2;
    const int acol = (tid & 3) * 8;
    const __half* Ap = A + (size_t)(bm + arow) * lda + acol;
    const __half* Bp = B + (size_t)(bn + arow) * K   + acol;

    const uint32_t sAbase = (uint32_t)__cvta_generic_to_shared(As);
    const uint32_t sBbase = (uint32_t)__cvta_generic_to_shared(Bs);
    const uint32_t sA = sAbase + (arow * PS + acol) * 2;
    const uint32_t sB = sBbase + (arow * PS + acol) * 2;

    const int nk = K / BK;

    auto issue = [&](int st, int kof) {
        uint32_t a = sA + st * (ASZ * 2);
        uint32_t b = sB + st * (BSZ * 2);
        cp_async16(a,                Ap + kof);
        cp_async16(a + 64 * PS * 2,  Ap + kof + (size_t)64 * lda);
        cp_async16(b,                Bp + kof);
        cp_async16(b + 64 * PS * 2,  Bp + kof + (size_t)64  * K);
        cp_async16(b + 128 * PS * 2, Bp + kof + (size_t)128 * K);
        cp_async16(b + 192 * PS * 2, Bp + kof + (size_t)192 * K);
        cp_commit();
    };

    float c[4][8][4];
#pragma unroll
    for (int mt = 0; mt < 4; mt++)
#pragma unroll
        for (int nt = 0; nt < 8; nt++)
#pragma unroll
            for (int j = 0; j < 4; j++) c[mt][nt][j] = 0.f;

    const int aOff = (wm * 64 + (lane & 15)) * PS + (lane >> 4) * 8;
    const int bOff = (wn * 64 + (lane & 7) + ((lane >> 4) & 1) * 8) * PS
                   + ((lane >> 3) & 1) * 8;

    issue(0, 0);
    issue(1, BK);
    issue(2, 2 * BK);

    for (int it = 0; it < nk; it++) {
        cp_wait<2>();
        __syncthreads();
        if (it + 3 < nk) issue((it + 3) & 3, (it + 3) * BK);
        else             cp_commit();

        const uint32_t aS = sAbase + ((it & 3) * ASZ) * 2;
        const uint32_t bS = sBbase + ((it & 3) * BSZ) * 2;
#pragma unroll
        for (int ks = 0; ks < 2; ks++) {
            uint32_t a[4][4], b[8][2];
#pragma unroll
            for (int mt = 0; mt < 4; mt++)
                ldsm4(a[mt][0], a[mt][1], a[mt][2], a[mt][3],
                      aS + (aOff + mt * 16 * PS + ks * 16) * 2);
#pragma unroll
            for (int np = 0; np < 4; np++)
                ldsm4(b[2 * np][0], b[2 * np][1], b[2 * np + 1][0], b[2 * np + 1][1],
                      bS + (bOff + np * 16 * PS + ks * 16) * 2);
#pragma unroll
            for (int mt = 0; mt < 4; mt++)
#pragma unroll
                for (int nt = 0; nt < 8; nt++)
                    mma16816(c[mt][nt], a[mt], b[nt]);
        }
    }

    const int g  = lane >> 2;
    const int tg = lane & 3;
#pragma unroll
    for (int mt = 0; mt < 4; mt++) {
        const int row = bm + wm * 64 + mt * 16 + g;
#pragma unroll
        for (int nt = 0; nt < 8; nt++) {
            const int col = bn + wn * 64 + nt * 8 + 2 * tg;
            const float bx = bias[col], by = bias[col + 1];
            float v0x = c[mt][nt][0] + bx, v0y = c[mt][nt][1] + by;
            float v1x = c[mt][nt][2] + bx, v1y = c[mt][nt][3] + by;
            if (GELU) {
                v0x = gelu_f(v0x); v0y = gelu_f(v0y);
                v1x = gelu_f(v1x); v1y = gelu_f(v1y);
            }
            if (HALFOUT) {
                __half* C = (__half*)Cv;
                *(__half2*)(C + (size_t)row * ldc + col)       = __floats2half2_rn(v0x, v0y);
                *(__half2*)(C + (size_t)(row + 8) * ldc + col) = __floats2half2_rn(v1x, v1y);
            } else {
                float* C = (float*)Cv;
                *(float2*)(C + (size_t)row * ldc + col)       = make_float2(v0x, v0y);
                *(float2*)(C + (size_t)(row + 8) * ldc + col) = make_float2(v1x, v1y);
            }
        }
    }
}

// ---------------------------------------------------------------------------
// fp32 -> fp16 conversion copy
// ---------------------------------------------------------------------------
__global__ void cvt_half(const float2* __restrict__ in,
                         __half2* __restrict__ out, int n2)
{
    int i = blockIdx.x * blockDim.x + threadIdx.x;
    if (i >= n2) return;
    float2 v = in[i];
    out[i] = __floats2half2_rn(v.x, v.y);
}

// ---------------------------------------------------------------------------
// pe-projection biases: peq[l][r][d] = pe[l][r] . Wq[l][d],  pek likewise.
// One warp per output (2*L*3*768 = 13824 warps).
// ---------------------------------------------------------------------------
__global__ void peb(const float* __restrict__ pos_emb,
                    const __half* __restrict__ w_aiw,
                    float* __restrict__ peq, float* __restrict__ pek)
{
    int gw   = (blockIdx.x * blockDim.x + threadIdx.x) >> 5;
    int lane = threadIdx.x & 31;
    if (gw >= 2 * Lm * 3 * Dm) return;
    int d  = gw % Dm;
    int t  = gw / Dm;          // 0..17
    int r  = t % 3;
    int qk = (t / 3) % 2;
    int l  = t / 6;

    const __half* wrow = w_aiw + ((size_t)l * 3 * Dm + qk * Dm + d) * Dm;
    const float*  pe   = pos_emb + (size_t)(l * 4 + r) * Dm;
    float s = 0.f;
#pragma unroll 4
    for (int j = lane; j < Dm; j += 32) s += pe[j] * __half2float(wrow[j]);
#pragma unroll
    for (int o = 16; o; o >>= 1) s += __shfl_xor_sync(0xffffffffu, s, o);
    if (lane == 0)
        (qk ? pek : peq)[(l * 3 + r) * Dm + d] = s;
}

// ---------------------------------------------------------------------------
// x construction: token 2n = parent[b], token 2n+1 = child[n^1]
// ---------------------------------------------------------------------------
__global__ void build_x(const float* __restrict__ parent,
                        const float* __restrict__ child)
{
    int idx = blockIdx.x * blockDim.x + threadIdx.x;
    if (idx >= TT * Dm) return;
    int t = idx / Dm;
    int d = idx - t * Dm;
    int n = t >> 1;
    float val;
    if ((t & 1) == 0) {
        int b = n >> 6;
        val = parent[b * Dm + d];
    } else {
        val = child[(size_t)(n ^ 1) * Dm + d];
    }
    g_x[idx]  = val;
    g_xh[idx] = __float2half_rn(val);
}

// ---------------------------------------------------------------------------
// 2x2 attention per (sequence, head). One warp per (n,h).
// Reads fused QKV (half) + per-role pe biases; writes half attn-out.
// ---------------------------------------------------------------------------
__global__ void attn2(const __half* __restrict__ qkv,
                      const float* __restrict__ peq,
                      const float* __restrict__ pek)
{
    int gw   = (blockIdx.x * blockDim.x + threadIdx.x) >> 5;
    int lane = threadIdx.x & 31;
    if (gw >= NSEQ * Hm) return;
    int n = gw / Hm;
    int h = gw - n * Hm;

    const int    pidx = h * 64 + 2 * lane;
    const size_t b0   = (size_t)(2 * n) * QKV + pidx;
    const size_t b1   = b0 + QKV;
    const int    r1   = 1 + (n & 1);

    float2 hq0 = __half22float2(*(const __half2*)(qkv + b0));
    float2 hk0 = __half22float2(*(const __half2*)(qkv + b0 + Dm));
    float2 v0  = __half22float2(*(const __half2*)(qkv + b0 + 2 * Dm));
    float2 hq1 = __half22float2(*(const __half2*)(qkv + b1));
    float2 hk1 = __half22float2(*(const __half2*)(qkv + b1 + Dm));
    float2 v1  = __half22float2(*(const __half2*)(qkv + b1 + 2 * Dm));

    float2 pq0 = *(const float2*)(peq + pidx);
    float2 pk0 = *(const float2*)(pek + pidx);
    float2 pq1 = *(const float2*)(peq + r1 * Dm + pidx);
    float2 pk1 = *(const float2*)(pek + r1 * Dm + pidx);

    float2 q0 = make_float2(hq0.x + pq0.x, hq0.y + pq0.y);
    float2 k0 = make_float2(hk0.x + pk0.x, hk0.y + pk0.y);
    float2 q1 = make_float2(hq1.x + pq1.x, hq1.y + pq1.y);
    float2 k1 = make_float2(hk1.x + pk1.x, hk1.y + pk1.y);

    float s00 = q0.x * k0.x + q0.y * k0.y;
    float s01 = q0.x * k1.x + q0.y * k1.y;
    float s10 = q1.x * k0.x + q1.y * k0.y;
    float s11 = q1.x * k1.x + q1.y * k1.y;
#pragma unroll
    for (int o = 16; o; o >>= 1) {
        s00 += __shfl_xor_sync(0xffffffffu, s00, o);
        s01 += __shfl_xor_sync(0xffffffffu, s01, o);
        s10 += __shfl_xor_sync(0xffffffffu, s10, o);
        s11 += __shfl_xor_sync(0xffffffffu, s11, o);
    }
    const float sc = 0.125f;
    s00 *= sc; s01 *= sc; s10 *= sc; s11 *= sc;

    float m0 = fmaxf(s00, s01), m1 = fmaxf(s10, s11);
    float e00 = __expf(s00 - m0), e01 = __expf(s01 - m0);
    float e10 = __expf(s10 - m1), e11 = __expf(s11 - m1);
    float r0 = 1.f / (e00 + e01), rr1 = 1.f / (e10 + e11);
    float a00 = e00 * r0, a01 = e01 * r0;
    float a10 = e10 * rr1, a11 = e11 * rr1;

    size_t vbase = (size_t)(2 * n) * Dm + pidx;
    *(__half2*)(g_ah + vbase) =
        __floats2half2_rn(a00 * v0.x + a01 * v1.x, a00 * v0.y + a01 * v1.y);
    *(__half2*)(g_ah + vbase + Dm) =
        __floats2half2_rn(a10 * v0.x + a11 * v1.x, a10 * v0.y + a11 * v1.y);
}

// ---------------------------------------------------------------------------
// Warp-reduce helper
// ---------------------------------------------------------------------------
__device__ __forceinline__ float wsum(float v) {
#pragma unroll
    for (int o = 16; o; o >>= 1) v += __shfl_xor_sync(0xffffffffu, v, o);
    return v;
}

// x = inorm(x + delta): one warp per row; fp32 state + half copy
__global__ void add_inorm(float* __restrict__ x, __half* __restrict__ xh,
                          const float* __restrict__ delta)
{
    int row  = (blockIdx.x * blockDim.x + threadIdx.x) >> 5;
    int lane = threadIdx.x & 31;
    if (row >= TT) return;
    size_t base = (size_t)row * Dm;
    const float4* xp = (const float4*)(x + base);
    const float4* dp = (const float4*)(delta + base);

    float4 v[6];
    float s = 0.f;
#pragma unroll
    for (int i = 0; i < 6; i++) {
        float4 a = xp[lane + 32 * i];
        float4 b = dp[lane + 32 * i];
        v[i].x = a.x + b.x; v[i].y = a.y + b.y;
        v[i].z = a.z + b.z; v[i].w = a.w + b.w;
        s += v[i].x + v[i].y + v[i].z + v[i].w;
    }
    float mean = wsum(s) * (1.f / 768.f);
    float vs = 0.f;
#pragma unroll
    for (int i = 0; i < 6; i++) {
        float dx = v[i].x - mean, dy = v[i].y - mean;
        float dz = v[i].z - mean, dw = v[i].w - mean;
        vs += dx * dx + dy * dy + dz * dz + dw * dw;
    }
    float rs = rsqrtf(wsum(vs) * (1.f / 768.f) + EPSf);

    float4*  xo = (float4*)(x + base);
    __half2* ho = (__half2*)(xh + base);
#pragma unroll
    for (int i = 0; i < 6; i++) {
        float4 r;
        r.x = (v[i].x - mean) * rs; r.y = (v[i].y - mean) * rs;
        r.z = (v[i].z - mean) * rs; r.w = (v[i].w - mean) * rs;
        xo[lane + 32 * i] = r;
        ho[(lane + 32 * i) * 2]     = __floats2half2_rn(r.x, r.y);
        ho[(lane + 32 * i) * 2 + 1] = __floats2half2_rn(r.z, r.w);
    }
}

// out_e[n] = inorm(x[2n] + x[2n+1]): one warp per sequence
__global__ void final_out(float* __restrict__ out)
{
    int n    = (blockIdx.x * blockDim.x + threadIdx.x) >> 5;
    int lane = threadIdx.x & 31;
    if (n >= NSEQ) return;
    size_t base = (size_t)(2 * n) * Dm;
    const float4* x0 = (const float4*)(g_x + base);
    const float4* x1 = (const float4*)(g_x + base + Dm);

    float4 v[6];
    float s = 0.f;
#pragma unroll
    for (int i = 0; i < 6; i++) {
        float4 a = x0[lane + 32 * i];
        float4 b = x1[lane + 32 * i];
        v[i].x = a.x + b.x; v[i].y = a.y + b.y;
        v[i].z = a.z + b.z; v[i].w = a.w + b.w;
        s += v[i].x + v[i].y + v[i].z + v[i].w;
    }
    float mean = wsum(s) * (1.f / 768.f);
    float vs = 0.f;
#pragma unroll
    for (int i = 0; i < 6; i++) {
        float dx = v[i].x - mean, dy = v[i].y - mean;
        float dz = v[i].z - mean, dw = v[i].w - mean;
        vs += dx * dx + dy * dy + dz * dz + dw * dw;
    }
    float rs = rsqrtf(wsum(vs) * (1.f / 768.f) + EPSf);

    float4* o = (float4*)(out + (size_t)n * Dm);
#pragma unroll
    for (int i = 0; i < 6; i++) {
        float4 r;
        r.x = (v[i].x - mean) * rs; r.y = (v[i].y - mean) * rs;
        r.z = (v[i].z - mean) * rs; r.w = (v[i].w - mean) * rs;
        o[lane + 32 * i] = r;
    }
}

__global__ void dot_scores(const float* __restrict__ pc,
                           const float* __restrict__ lc,
                           const float* __restrict__ rc,
                           float* __restrict__ out)
{
    int gw   = (blockIdx.x * blockDim.x + threadIdx.x) >> 5;
    int lane = threadIdx.x & 31;
    if (gw >= NSEQ) return;
    int i     = gw >> 1;
    int which = gw & 1;
    int b     = i >> 5;
    const float* u = pc + b * CSm;
    const float* w = (which == 0 ? rc : lc) + (size_t)i * CSm;
    float s = 0.f;
#pragma unroll 4
    for (int j = lane; j < CSm; j += 32) s += u[j] * w[j];
    s = wsum(s);
    if (lane == 0) out[gw] = s * 0.044194173824159216f;
}

// ---------------------------------------------------------------------------
// Host launcher
// ---------------------------------------------------------------------------
static void* devptr(const void* sym)
{
    void* p = nullptr;
    cudaGetSymbolAddress(&p, sym);
    return p;
}

extern "C" void kernel_launch(void* const* d_in, const int* in_sizes, int n_in,
                              void* d_out, int out_size)
{
    (void)in_sizes; (void)n_in; (void)out_size;

    const float* parent     = (const float*)d_in[0];
    const float* child      = (const float*)d_in[1];
    const float* attn_in_w  = (const float*)d_in[4];
    const float* attn_in_b  = (const float*)d_in[5];
    const float* attn_out_w = (const float*)d_in[6];
    const float* attn_out_b = (const float*)d_in[7];
    const float* lin1_w     = (const float*)d_in[8];
    const float* lin1_b     = (const float*)d_in[9];
    const float* lin2_w     = (const float*)d_in[10];
    const float* lin2_b     = (const float*)d_in[11];
    const float* pos_emb    = (const float*)d_in[12];
    const float* parent_w1  = (const float*)d_in[13];
    const float* parent_b1  = (const float*)d_in[14];
    const float* parent_w2  = (const float*)d_in[15];
    const float* parent_b2  = (const float*)d_in[16];
    const float* left_w1    = (const float*)d_in[17];
    const float* left_b1    = (const float*)d_in[18];
    const float* left_w2    = (const float*)d_in[19];
    const float* left_b2    = (const float*)d_in[20];
    const float* right_w1   = (const float*)d_in[21];
    const float* right_b1   = (const float*)d_in[22];
    const float* right_w2   = (const float*)d_in[23];
    const float* right_b2   = (const float*)d_in[24];
    float* out = (float*)d_out;

    float*  px   = (float*) devptr(g_x);
    float*  pt   = (float*) devptr(g_t);
    float*  ppeq = (float*) devptr(g_peq);
    float*  ppek = (float*) devptr(g_pek);
    __half* pqkv = (__half*)devptr(g_qkvh);
    __half* pxh  = (__half*)devptr(g_xh);
    __half* pah  = (__half*)devptr(g_ah);
    __half* phid = (__half*)devptr(g_hidh);
    __half* pwh  = (__half*)devptr(g_wh);
    __half* pch  = (__half*)devptr(g_ch);
    __half* pph  = (__half*)devptr(g_ph);

    constexpr int SMEMB = (4 * 128 * PS + 4 * 256 * PS) * 2;   // 122880 B
    static int attr_done = 0;
    if (!attr_done) {
        cudaFuncSetAttribute(hgemm<false, false>,
                             cudaFuncAttributeMaxDynamicSharedMemorySize, SMEMB);
        cudaFuncSetAttribute(hgemm<false, true>,
                             cudaFuncAttributeMaxDynamicSharedMemorySize, SMEMB);
        cudaFuncSetAttribute(hgemm<true, true>,
                             cudaFuncAttributeMaxDynamicSharedMemorySize, SMEMB);
        attr_done = 1;
    }

    // ---- weight / input fp16 conversion (offsets into g_wh) ----
    const int n_aiw = Lm * 3 * Dm * Dm;
    const int n_aow = Lm * Dm * Dm;
    const int n_l1  = Lm * FFm * Dm;
    const int n_l2  = Lm * Dm * FFm;
    const int n_w1  = Dm * Dm;
    const int n_w2  = CSm * Dm;

    __half* w_aiw = pwh;
    __half* w_aow = w_aiw + n_aiw;
    __half* w_l1  = w_aow + n_aow;
    __half* w_l2  = w_l1  + n_l1;
    __half* w_pw1 = w_l2  + n_l2;
    __half* w_pw2 = w_pw1 + n_w1;
    __half* w_lw1 = w_pw2 + n_w2;
    __half* w_lw2 = w_lw1 + n_w1;
    __half* w_rw1 = w_lw2 + n_w2;
    __half* w_rw2 = w_rw1 + n_w1;

    struct CV { const float* src; __half* dst; int n; };
    CV cvs[] = {
        {attn_in_w,  w_aiw, n_aiw}, {attn_out_w, w_aow, n_aow},
        {lin1_w,     w_l1,  n_l1},  {lin2_w,     w_l2,  n_l2},
        {parent_w1,  w_pw1, n_w1},  {parent_w2,  w_pw2, n_w2},
        {left_w1,    w_lw1, n_w1},  {left_w2,    w_lw2, n_w2},
        {right_w1,   w_rw1, n_w1},  {right_w2,   w_rw2, n_w2},
        {child,      pch,   NSEQ * Dm}, {parent, pph,   Bm * Dm},
    };
    for (auto& c : cvs) {
        int n2 = c.n / 2;
        cvt_half<<<(n2 + 255) / 256, 256>>>(
            (const float2*)c.src, (__half2*)c.dst, n2);
    }

    // pe @ W{q,k}^T biases (needs w_aiw; stream-ordered after cvts)
    peb<<<(2 * Lm * 3 * Dm * 32) / 256, 256>>>(pos_emb, w_aiw, ppeq, ppek);

    const int EW = (TT * Dm) / 256;
    build_x<<<EW, 256>>>(parent, child);

    // ---- outside-score path ----
    {
        __half* h_par = pah;                         // 256 x 768
        __half* h_lft = pah + (size_t)Bm * Dm;       // 8192 x 768
        __half* h_rgt = pah + (size_t)(Bm + 8192) * Dm;
        float*  o_pc  = pt;                          // 256 x 512
        float*  o_lc  = pt + (size_t)Bm * CSm;
        float*  o_rc  = pt + (size_t)(Bm + 8192) * CSm;

        hgemm<true , true ><<<dim3(3, 2),  256, SMEMB>>>(pph,      Dm,     w_pw1, parent_b1, h_par, Dm,  Dm);
        hgemm<false, false><<<dim3(2, 2),  256, SMEMB>>>(h_par,    Dm,     w_pw2, parent_b2, o_pc,  CSm, Dm);
        hgemm<true , true ><<<dim3(3, 64), 256, SMEMB>>>(pch,      2 * Dm, w_lw1, left_b1,   h_lft, Dm,  Dm);
        hgemm<false, false><<<dim3(2, 64), 256, SMEMB>>>(h_lft,    Dm,     w_lw2, left_b2,   o_lc,  CSm, Dm);
        hgemm<true , true ><<<dim3(3, 64), 256, SMEMB>>>(pch + Dm, 2 * Dm, w_rw1, right_b1,  h_rgt, Dm,  Dm);
        hgemm<false, false><<<dim3(2, 64), 256, SMEMB>>>(h_rgt,    Dm,     w_rw2, right_b2,  o_rc,  CSm, Dm);
        dot_scores<<<(NSEQ * 32) / 256, 256>>>(o_pc, o_lc, o_rc, out);
    }

    // ---- 3 tree-transformer layers ----
    dim3 gQKV(QKV / 256, TT / 128);    // (9, 256)
    dim3 gD  (Dm  / 256, TT / 128);    // (3, 256)
    dim3 gM1 (FFm / 256, TT / 128);    // (12, 256)

    for (int l = 0; l < Lm; l++) {
        const __half* iw = w_aiw + (size_t)l * 3 * Dm * Dm;
        const float*  ib = attn_in_b  + (size_t)l * 3 * Dm;
        const __half* ow = w_aow + (size_t)l * Dm * Dm;
        const float*  ob = attn_out_b + (size_t)l * Dm;
        const __half* w1 = w_l1  + (size_t)l * FFm * Dm;
        const float*  b1 = lin1_b     + (size_t)l * FFm;
        const __half* w2 = w_l2  + (size_t)l * Dm * FFm;
        const float*  b2 = lin2_b     + (size_t)l * Dm;

        // fused QKV = x @ [Wq;Wk;Wv]^T + [bq;bk;bv]   (pe handled in attn2)
        hgemm<false, true ><<<gQKV, 256, SMEMB>>>(pxh, Dm, iw, ib, pqkv, QKV, Dm);
        attn2<<<(NSEQ * Hm * 32) / 256, 256>>>(pqkv,
                                               ppeq + (size_t)l * 3 * Dm,
                                               ppek + (size_t)l * 3 * Dm);
        hgemm<false, false><<<gD , 256, SMEMB>>>(pah, Dm, ow, ob, pt, Dm, Dm);
        add_inorm<<<(TT * 32) / 256, 256>>>(px, pxh, pt);
        hgemm<true , true ><<<gM1, 256, SMEMB>>>(pxh,  Dm,  w1, b1, phid, FFm, Dm);
        hgemm<false, false><<<gD , 256, SMEMB>>>(phid, FFm, w2, b2, pt,   Dm,  FFm);
        add_inorm<<<(TT * 32) / 256, 256>>>(px, pxh, pt);
    }

    final_out<<<(NSEQ * 32) / 256, 256>>>(out + NSEQ);
}

// round 7
// speedup vs baseline: 5.8155x; 1.0452x over previous
#include <cuda_runtime.h>
#include <cuda_fp16.h>
#include <math.h>
#include <stdint.h>

// ---------------------------------------------------------------------------
// Problem constants
// ---------------------------------------------------------------------------
namespace {
constexpr int Dm   = 768;
constexpr int FFm  = 3072;
constexpr int Hm   = 12;
constexpr int Lm   = 3;
constexpr int CSm  = 512;
constexpr int Bm   = 256;
constexpr int NSEQ = 16384;         // sequences of 2 tokens
constexpr int TT   = NSEQ * 2;      // 32768 tokens
constexpr float EPSf = 1e-5f;
constexpr int PS   = 40;            // gemm smem row stride in halves (80 B)
constexpr int QKV  = 2304;          // fused QKV width
}

// ---------------------------------------------------------------------------
// Scratch (device globals; no runtime allocation allowed)
// ---------------------------------------------------------------------------
__device__ float g_x [TT * Dm];                    // fp32 residual state
__device__ float g_t [TT * Dm];                    // fp32 GEMM outs / lc,rc,pc
__device__ float g_peq[Lm * 3 * Dm];               // pe @ Wq^T per (layer,role)
__device__ float g_pek[Lm * 3 * Dm];               // pe @ Wk^T per (layer,role)
__device__ __align__(16) __half g_qkvh[TT * QKV];  // fused QKV (half)
__device__ __align__(16) __half g_xh  [TT * Dm];   // half copy of x
__device__ __align__(16) __half g_ah  [TT * Dm];   // attn-out / score hiddens
__device__ __align__(16) __half g_hidh[TT * FFm];  // MLP hidden (half)
__device__ __align__(16) __half g_wh  [24182784];  // all weights, half
__device__ __align__(16) __half g_ch  [TT * Dm];   // child, half
__device__ __align__(16) __half g_ph  [Bm * Dm];   // parent, half

__device__ __forceinline__ float gelu_f(float x) {
    return 0.5f * x * (1.0f + erff(x * 0.7071067811865475f));
}

__device__ __forceinline__ void cp_async16(uint32_t s, const void* g) {
    asm volatile("cp.async.cg.shared.global [%0], [%1], 16;\n" :: "r"(s), "l"(g));
}
__device__ __forceinline__ void cp_commit() {
    asm volatile("cp.async.commit_group;\n");
}
template <int N> __device__ __forceinline__ void cp_wait() {
    asm volatile("cp.async.wait_group %0;\n" :: "n"(N));
}
__device__ __forceinline__ void ldsm4(uint32_t& r0, uint32_t& r1,
                                      uint32_t& r2, uint32_t& r3, uint32_t addr) {
    asm volatile("ldmatrix.sync.aligned.m8n8.x4.shared.b16 {%0,%1,%2,%3}, [%4];"
                 : "=r"(r0), "=r"(r1), "=r"(r2), "=r"(r3) : "r"(addr));
}
__device__ __forceinline__ void mma16816(float* c, const uint32_t* a, const uint32_t* b) {
    asm volatile(
        "mma.sync.aligned.m16n8k16.row.col.f32.f16.f16.f32 "
        "{%0,%1,%2,%3}, {%4,%5,%6,%7}, {%8,%9}, {%0,%1,%2,%3};"
        : "+f"(c[0]), "+f"(c[1]), "+f"(c[2]), "+f"(c[3])
        : "r"(a[0]), "r"(a[1]), "r"(a[2]), "r"(a[3]), "r"(b[0]), "r"(b[1]));
}

// ---------------------------------------------------------------------------
// Shared GEMM body: CTA 128x256, 8 warps (2m x 4n), warp tile 64x64, BK=32,
// m16n8k16 HMMA + ldmatrix.x4, 4-stage cp.async pipeline. (proven R4/R6)
// ---------------------------------------------------------------------------
template <bool GELU, bool HALFOUT>
__device__ __forceinline__ void gemm_body(
    const __half* __restrict__ A, int lda,
    const __half* __restrict__ B, const float* __restrict__ bias,
    void* __restrict__ Cv, int ldc, int K, int bm, int bn, __half* sh)
{
    constexpr int BM = 128, BN = 256, BK = 32;
    constexpr int ASZ = BM * PS;
    constexpr int BSZ = BN * PS;
    __half* As = sh;
    __half* Bs = sh + 4 * ASZ;

    const int tid  = threadIdx.x;
    const int lane = tid & 31;
    const int wid  = tid >> 5;
    const int wm   = wid >> 2;
    const int wn   = wid & 3;

    const int arow = tid >> 2;
    const int acol = (tid & 3) * 8;
    const __half* Ap = A + (size_t)(bm + arow) * lda + acol;
    const __half* Bp = B + (size_t)(bn + arow) * K   + acol;

    const uint32_t sAbase = (uint32_t)__cvta_generic_to_shared(As);
    const uint32_t sBbase = (uint32_t)__cvta_generic_to_shared(Bs);
    const uint32_t sA = sAbase + (arow * PS + acol) * 2;
    const uint32_t sB = sBbase + (arow * PS + acol) * 2;

    const int nk = K / BK;

    auto issue = [&](int st, int kof) {
        uint32_t a = sA + st * (ASZ * 2);
        uint32_t b = sB + st * (BSZ * 2);
        cp_async16(a,                Ap + kof);
        cp_async16(a + 64 * PS * 2,  Ap + kof + (size_t)64 * lda);
        cp_async16(b,                Bp + kof);
        cp_async16(b + 64 * PS * 2,  Bp + kof + (size_t)64  * K);
        cp_async16(b + 128 * PS * 2, Bp + kof + (size_t)128 * K);
        cp_async16(b + 192 * PS * 2, Bp + kof + (size_t)192 * K);
        cp_commit();
    };

    float c[4][8][4];
#pragma unroll
    for (int mt = 0; mt < 4; mt++)
#pragma unroll
        for (int nt = 0; nt < 8; nt++)
#pragma unroll
            for (int j = 0; j < 4; j++) c[mt][nt][j] = 0.f;

    const int aOff = (wm * 64 + (lane & 15)) * PS + (lane >> 4) * 8;
    const int bOff = (wn * 64 + (lane & 7) + ((lane >> 4) & 1) * 8) * PS
                   + ((lane >> 3) & 1) * 8;

    issue(0, 0);
    issue(1, BK);
    issue(2, 2 * BK);

    for (int it = 0; it < nk; it++) {
        cp_wait<2>();
        __syncthreads();
        if (it + 3 < nk) issue((it + 3) & 3, (it + 3) * BK);
        else             cp_commit();

        const uint32_t aS = sAbase + ((it & 3) * ASZ) * 2;
        const uint32_t bS = sBbase + ((it & 3) * BSZ) * 2;
#pragma unroll
        for (int ks = 0; ks < 2; ks++) {
            uint32_t a[4][4], b[8][2];
#pragma unroll
            for (int mt = 0; mt < 4; mt++)
                ldsm4(a[mt][0], a[mt][1], a[mt][2], a[mt][3],
                      aS + (aOff + mt * 16 * PS + ks * 16) * 2);
#pragma unroll
            for (int np = 0; np < 4; np++)
                ldsm4(b[2 * np][0], b[2 * np][1], b[2 * np + 1][0], b[2 * np + 1][1],
                      bS + (bOff + np * 16 * PS + ks * 16) * 2);
#pragma unroll
            for (int mt = 0; mt < 4; mt++)
#pragma unroll
                for (int nt = 0; nt < 8; nt++)
                    mma16816(c[mt][nt], a[mt], b[nt]);
        }
    }

    const int g  = lane >> 2;
    const int tg = lane & 3;
#pragma unroll
    for (int mt = 0; mt < 4; mt++) {
        const int row = bm + wm * 64 + mt * 16 + g;
#pragma unroll
        for (int nt = 0; nt < 8; nt++) {
            const int col = bn + wn * 64 + nt * 8 + 2 * tg;
            const float bx = bias[col], by = bias[col + 1];
            float v0x = c[mt][nt][0] + bx, v0y = c[mt][nt][1] + by;
            float v1x = c[mt][nt][2] + bx, v1y = c[mt][nt][3] + by;
            if (GELU) {
                v0x = gelu_f(v0x); v0y = gelu_f(v0y);
                v1x = gelu_f(v1x); v1y = gelu_f(v1y);
            }
            if (HALFOUT) {
                __half* C = (__half*)Cv;
                *(__half2*)(C + (size_t)row * ldc + col)       = __floats2half2_rn(v0x, v0y);
                *(__half2*)(C + (size_t)(row + 8) * ldc + col) = __floats2half2_rn(v1x, v1y);
            } else {
                float* C = (float*)Cv;
                *(float2*)(C + (size_t)row * ldc + col)       = make_float2(v0x, v0y);
                *(float2*)(C + (size_t)(row + 8) * ldc + col) = make_float2(v1x, v1y);
            }
        }
    }
}

template <bool GELU, bool HALFOUT>
__global__ void __launch_bounds__(256, 1) hgemm(
    const __half* __restrict__ A, int lda,
    const __half* __restrict__ B, const float* __restrict__ bias,
    void* __restrict__ Cv, int ldc, int K)
{
    extern __shared__ __half sh[];
    gemm_body<GELU, HALFOUT>(A, lda, B, bias, Cv, ldc, K,
                             blockIdx.y * 128, blockIdx.x * 256, sh);
}

// 3-segment batched GEMM: blockIdx.y range selects (A,lda,B,bias,C)
template <bool GELU, bool HALFOUT>
__global__ void __launch_bounds__(256, 1) hgemm_b3(
    const __half* A0, int lda0, const __half* B0, const float* bias0, void* C0,
    const __half* A1, int lda1, const __half* B1, const float* bias1, void* C1,
    const __half* A2, int lda2, const __half* B2, const float* bias2, void* C2,
    int y1, int y2, int ldc, int K)
{
    extern __shared__ __half sh[];
    const int y = blockIdx.y;
    const __half* A; int lda; const __half* B; const float* bias; void* C; int ly;
    if (y < y1)      { A = A0; lda = lda0; B = B0; bias = bias0; C = C0; ly = y; }
    else if (y < y2) { A = A1; lda = lda1; B = B1; bias = bias1; C = C1; ly = y - y1; }
    else             { A = A2; lda = lda2; B = B2; bias = bias2; C = C2; ly = y - y2; }
    gemm_body<GELU, HALFOUT>(A, lda, B, bias, C, ldc, K,
                             ly * 128, blockIdx.x * 256, sh);
}

// ---------------------------------------------------------------------------
// Fused fp32 -> fp16 conversion for all segments (single launch)
// ---------------------------------------------------------------------------
struct CvtArgs {
    const float2* src[12];
    __half2*      dst[12];
    int           end[12];    // cumulative end (in float2 units)
};
__global__ void cvt_all(CvtArgs a, int total2)
{
    int i = blockIdx.x * blockDim.x + threadIdx.x;
    if (i >= total2) return;
    int s = 0;
#pragma unroll
    for (int k = 0; k < 11; k++) s += (i >= a.end[s]) ? 1 : 0;
    int base = s ? a.end[s - 1] : 0;
    float2 v = a.src[s][i - base];
    a.dst[s][i - base] = __floats2half2_rn(v.x, v.y);
}

// ---------------------------------------------------------------------------
// pe-projection biases: peq[l][r][d] = pe[l][r] . Wq[l][d],  pek likewise.
// ---------------------------------------------------------------------------
__global__ void peb(const float* __restrict__ pos_emb,
                    const __half* __restrict__ w_aiw,
                    float* __restrict__ peq, float* __restrict__ pek)
{
    int gw   = (blockIdx.x * blockDim.x + threadIdx.x) >> 5;
    int lane = threadIdx.x & 31;
    if (gw >= 2 * Lm * 3 * Dm) return;
    int d  = gw % Dm;
    int t  = gw / Dm;
    int r  = t % 3;
    int qk = (t / 3) % 2;
    int l  = t / 6;

    const __half* wrow = w_aiw + ((size_t)l * 3 * Dm + qk * Dm + d) * Dm;
    const float*  pe   = pos_emb + (size_t)(l * 4 + r) * Dm;
    float s = 0.f;
#pragma unroll 4
    for (int j = lane; j < Dm; j += 32) s += pe[j] * __half2float(wrow[j]);
#pragma unroll
    for (int o = 16; o; o >>= 1) s += __shfl_xor_sync(0xffffffffu, s, o);
    if (lane == 0)
        (qk ? pek : peq)[(l * 3 + r) * Dm + d] = s;
}

// ---------------------------------------------------------------------------
// x construction: token 2n = parent[b], token 2n+1 = child[n^1]
// ---------------------------------------------------------------------------
__global__ void build_x(const float* __restrict__ parent,
                        const float* __restrict__ child)
{
    int idx = blockIdx.x * blockDim.x + threadIdx.x;
    if (idx >= TT * Dm) return;
    int t = idx / Dm;
    int d = idx - t * Dm;
    int n = t >> 1;
    float val;
    if ((t & 1) == 0) {
        int b = n >> 6;
        val = parent[b * Dm + d];
    } else {
        val = child[(size_t)(n ^ 1) * Dm + d];
    }
    g_x[idx]  = val;
    g_xh[idx] = __float2half_rn(val);
}

// ---------------------------------------------------------------------------
// 2x2 attention per (sequence, head). One warp per (n,h).
// L1 variant reads deduped QKV: parent rows by b, child rows by n^1.
// ---------------------------------------------------------------------------
template <bool L1>
__global__ void attn2(const __half* __restrict__ qkv,
                      const __half* __restrict__ qkv_p,
                      const float* __restrict__ peq,
                      const float* __restrict__ pek)
{
    int gw   = (blockIdx.x * blockDim.x + threadIdx.x) >> 5;
    int lane = threadIdx.x & 31;
    if (gw >= NSEQ * Hm) return;
    int n = gw / Hm;
    int h = gw - n * Hm;

    const int pidx = h * 64 + 2 * lane;
    size_t b0, b1;
    const __half* src0;
    if (L1) {
        src0 = qkv_p;
        b0 = (size_t)(n >> 6) * QKV + pidx;       // parent row b
        b1 = (size_t)(n ^ 1) * QKV + pidx;        // child row n^1
    } else {
        src0 = qkv;
        b0 = (size_t)(2 * n) * QKV + pidx;
        b1 = b0 + QKV;
    }
    const int r1 = 1 + (n & 1);

    float2 hq0 = __half22float2(*(const __half2*)(src0 + b0));
    float2 hk0 = __half22float2(*(const __half2*)(src0 + b0 + Dm));
    float2 v0  = __half22float2(*(const __half2*)(src0 + b0 + 2 * Dm));
    float2 hq1 = __half22float2(*(const __half2*)(qkv + b1));
    float2 hk1 = __half22float2(*(const __half2*)(qkv + b1 + Dm));
    float2 v1  = __half22float2(*(const __half2*)(qkv + b1 + 2 * Dm));

    float2 pq0 = *(const float2*)(peq + pidx);
    float2 pk0 = *(const float2*)(pek + pidx);
    float2 pq1 = *(const float2*)(peq + r1 * Dm + pidx);
    float2 pk1 = *(const float2*)(pek + r1 * Dm + pidx);

    float2 q0 = make_float2(hq0.x + pq0.x, hq0.y + pq0.y);
    float2 k0 = make_float2(hk0.x + pk0.x, hk0.y + pk0.y);
    float2 q1 = make_float2(hq1.x + pq1.x, hq1.y + pq1.y);
    float2 k1 = make_float2(hk1.x + pk1.x, hk1.y + pk1.y);

    float s00 = q0.x * k0.x + q0.y * k0.y;
    float s01 = q0.x * k1.x + q0.y * k1.y;
    float s10 = q1.x * k0.x + q1.y * k0.y;
    float s11 = q1.x * k1.x + q1.y * k1.y;
#pragma unroll
    for (int o = 16; o; o >>= 1) {
        s00 += __shfl_xor_sync(0xffffffffu, s00, o);
        s01 += __shfl_xor_sync(0xffffffffu, s01, o);
        s10 += __shfl_xor_sync(0xffffffffu, s10, o);
        s11 += __shfl_xor_sync(0xffffffffu, s11, o);
    }
    const float sc = 0.125f;
    s00 *= sc; s01 *= sc; s10 *= sc; s11 *= sc;

    float m0 = fmaxf(s00, s01), m1 = fmaxf(s10, s11);
    float e00 = __expf(s00 - m0), e01 = __expf(s01 - m0);
    float e10 = __expf(s10 - m1), e11 = __expf(s11 - m1);
    float r0 = 1.f / (e00 + e01), rr1 = 1.f / (e10 + e11);
    float a00 = e00 * r0, a01 = e01 * r0;
    float a10 = e10 * rr1, a11 = e11 * rr1;

    size_t vbase = (size_t)(2 * n) * Dm + pidx;
    *(__half2*)(g_ah + vbase) =
        __floats2half2_rn(a00 * v0.x + a01 * v1.x, a00 * v0.y + a01 * v1.y);
    *(__half2*)(g_ah + vbase + Dm) =
        __floats2half2_rn(a10 * v0.x + a11 * v1.x, a10 * v0.y + a11 * v1.y);
}

// ---------------------------------------------------------------------------
// Warp-reduce helper
// ---------------------------------------------------------------------------
__device__ __forceinline__ float wsum(float v) {
#pragma unroll
    for (int o = 16; o; o >>= 1) v += __shfl_xor_sync(0xffffffffu, v, o);
    return v;
}

// x = inorm(x + delta): one warp per row; fp32 state + half copy
__global__ void add_inorm(float* __restrict__ x, __half* __restrict__ xh,
                          const float* __restrict__ delta)
{
    int row  = (blockIdx.x * blockDim.x + threadIdx.x) >> 5;
    int lane = threadIdx.x & 31;
    if (row >= TT) return;
    size_t base = (size_t)row * Dm;
    const float4* xp = (const float4*)(x + base);
    const float4* dp = (const float4*)(delta + base);

    float4 v[6];
    float s = 0.f;
#pragma unroll
    for (int i = 0; i < 6; i++) {
        float4 a = xp[lane + 32 * i];
        float4 b = dp[lane + 32 * i];
        v[i].x = a.x + b.x; v[i].y = a.y + b.y;
        v[i].z = a.z + b.z; v[i].w = a.w + b.w;
        s += v[i].x + v[i].y + v[i].z + v[i].w;
    }
    float mean = wsum(s) * (1.f / 768.f);
    float vs = 0.f;
#pragma unroll
    for (int i = 0; i < 6; i++) {
        float dx = v[i].x - mean, dy = v[i].y - mean;
        float dz = v[i].z - mean, dw = v[i].w - mean;
        vs += dx * dx + dy * dy + dz * dz + dw * dw;
    }
    float rs = rsqrtf(wsum(vs) * (1.f / 768.f) + EPSf);

    float4*  xo = (float4*)(x + base);
    __half2* ho = (__half2*)(xh + base);
#pragma unroll
    for (int i = 0; i < 6; i++) {
        float4 r;
        r.x = (v[i].x - mean) * rs; r.y = (v[i].y - mean) * rs;
        r.z = (v[i].z - mean) * rs; r.w = (v[i].w - mean) * rs;
        xo[lane + 32 * i] = r;
        ho[(lane + 32 * i) * 2]     = __floats2half2_rn(r.x, r.y);
        ho[(lane + 32 * i) * 2 + 1] = __floats2half2_rn(r.z, r.w);
    }
}

// out_e[n] = inorm(x[2n] + x[2n+1]): one warp per sequence
__global__ void final_out(float* __restrict__ out)
{
    int n    = (blockIdx.x * blockDim.x + threadIdx.x) >> 5;
    int lane = threadIdx.x & 31;
    if (n >= NSEQ) return;
    size_t base = (size_t)(2 * n) * Dm;
    const float4* x0 = (const float4*)(g_x + base);
    const float4* x1 = (const float4*)(g_x + base + Dm);

    float4 v[6];
    float s = 0.f;
#pragma unroll
    for (int i = 0; i < 6; i++) {
        float4 a = x0[lane + 32 * i];
        float4 b = x1[lane + 32 * i];
        v[i].x = a.x + b.x; v[i].y = a.y + b.y;
        v[i].z = a.z + b.z; v[i].w = a.w + b.w;
        s += v[i].x + v[i].y + v[i].z + v[i].w;
    }
    float mean = wsum(s) * (1.f / 768.f);
    float vs = 0.f;
#pragma unroll
    for (int i = 0; i < 6; i++) {
        float dx = v[i].x - mean, dy = v[i].y - mean;
        float dz = v[i].z - mean, dw = v[i].w - mean;
        vs += dx * dx + dy * dy + dz * dz + dw * dw;
    }
    float rs = rsqrtf(wsum(vs) * (1.f / 768.f) + EPSf);

    float4* o = (float4*)(out + (size_t)n * Dm);
#pragma unroll
    for (int i = 0; i < 6; i++) {
        float4 r;
        r.x = (v[i].x - mean) * rs; r.y = (v[i].y - mean) * rs;
        r.z = (v[i].z - mean) * rs; r.w = (v[i].w - mean) * rs;
        o[lane + 32 * i] = r;
    }
}

__global__ void dot_scores(const float* __restrict__ pc,
                           const float* __restrict__ lc,
                           const float* __restrict__ rc,
                           float* __restrict__ out)
{
    int gw   = (blockIdx.x * blockDim.x + threadIdx.x) >> 5;
    int lane = threadIdx.x & 31;
    if (gw >= NSEQ) return;
    int i     = gw >> 1;
    int which = gw & 1;
    int b     = i >> 5;
    const float* u = pc + b * CSm;
    const float* w = (which == 0 ? rc : lc) + (size_t)i * CSm;
    float s = 0.f;
#pragma unroll 4
    for (int j = lane; j < CSm; j += 32) s += u[j] * w[j];
    s = wsum(s);
    if (lane == 0) out[gw] = s * 0.044194173824159216f;
}

// ---------------------------------------------------------------------------
// Host launcher
// ---------------------------------------------------------------------------
static void* devptr(const void* sym)
{
    void* p = nullptr;
    cudaGetSymbolAddress(&p, sym);
    return p;
}

extern "C" void kernel_launch(void* const* d_in, const int* in_sizes, int n_in,
                              void* d_out, int out_size)
{
    (void)in_sizes; (void)n_in; (void)out_size;

    const float* parent     = (const float*)d_in[0];
    const float* child      = (const float*)d_in[1];
    const float* attn_in_w  = (const float*)d_in[4];
    const float* attn_in_b  = (const float*)d_in[5];
    const float* attn_out_w = (const float*)d_in[6];
    const float* attn_out_b = (const float*)d_in[7];
    const float* lin1_w     = (const float*)d_in[8];
    const float* lin1_b     = (const float*)d_in[9];
    const float* lin2_w     = (const float*)d_in[10];
    const float* lin2_b     = (const float*)d_in[11];
    const float* pos_emb    = (const float*)d_in[12];
    const float* parent_w1  = (const float*)d_in[13];
    const float* parent_b1  = (const float*)d_in[14];
    const float* parent_w2  = (const float*)d_in[15];
    const float* parent_b2  = (const float*)d_in[16];
    const float* left_w1    = (const float*)d_in[17];
    const float* left_b1    = (const float*)d_in[18];
    const float* left_w2    = (const float*)d_in[19];
    const float* left_b2    = (const float*)d_in[20];
    const float* right_w1   = (const float*)d_in[21];
    const float* right_b1   = (const float*)d_in[22];
    const float* right_w2   = (const float*)d_in[23];
    const float* right_b2   = (const float*)d_in[24];
    float* out = (float*)d_out;

    float*  px   = (float*) devptr(g_x);
    float*  pt   = (float*) devptr(g_t);
    float*  ppeq = (float*) devptr(g_peq);
    float*  ppek = (float*) devptr(g_pek);
    __half* pqkv = (__half*)devptr(g_qkvh);
    __half* pxh  = (__half*)devptr(g_xh);
    __half* pah  = (__half*)devptr(g_ah);
    __half* phid = (__half*)devptr(g_hidh);
    __half* pwh  = (__half*)devptr(g_wh);
    __half* pch  = (__half*)devptr(g_ch);
    __half* pph  = (__half*)devptr(g_ph);

    constexpr int SMEMB = (4 * 128 * PS + 4 * 256 * PS) * 2;   // 122880 B
    static int attr_done = 0;
    if (!attr_done) {
        cudaFuncSetAttribute(hgemm<false, false>,
                             cudaFuncAttributeMaxDynamicSharedMemorySize, SMEMB);
        cudaFuncSetAttribute(hgemm<false, true>,
                             cudaFuncAttributeMaxDynamicSharedMemorySize, SMEMB);
        cudaFuncSetAttribute(hgemm<true, true>,
                             cudaFuncAttributeMaxDynamicSharedMemorySize, SMEMB);
        cudaFuncSetAttribute(hgemm_b3<true, true>,
                             cudaFuncAttributeMaxDynamicSharedMemorySize, SMEMB);
        cudaFuncSetAttribute(hgemm_b3<false, false>,
                             cudaFuncAttributeMaxDynamicSharedMemorySize, SMEMB);
        cudaFuncSetAttribute(hgemm_b3<false, true>,
                             cudaFuncAttributeMaxDynamicSharedMemorySize, SMEMB);
        attr_done = 1;
    }

    // ---- fp16 conversion layout (offsets into g_wh) ----
    const int n_aiw = Lm * 3 * Dm * Dm;
    const int n_aow = Lm * Dm * Dm;
    const int n_l1  = Lm * FFm * Dm;
    const int n_l2  = Lm * Dm * FFm;
    const int n_w1  = Dm * Dm;
    const int n_w2  = CSm * Dm;

    __half* w_aiw = pwh;
    __half* w_aow = w_aiw + n_aiw;
    __half* w_l1  = w_aow + n_aow;
    __half* w_l2  = w_l1  + n_l1;
    __half* w_pw1 = w_l2  + n_l2;
    __half* w_pw2 = w_pw1 + n_w1;
    __half* w_lw1 = w_pw2 + n_w2;
    __half* w_lw2 = w_lw1 + n_w1;
    __half* w_rw1 = w_lw2 + n_w2;
    __half* w_rw2 = w_rw1 + n_w1;

    // single fused conversion launch
    {
        struct S { const float* s; __half* d; int n; };
        S segs[12] = {
            {attn_in_w,  w_aiw, n_aiw}, {attn_out_w, w_aow, n_aow},
            {lin1_w,     w_l1,  n_l1},  {lin2_w,     w_l2,  n_l2},
            {parent_w1,  w_pw1, n_w1},  {parent_w2,  w_pw2, n_w2},
            {left_w1,    w_lw1, n_w1},  {left_w2,    w_lw2, n_w2},
            {right_w1,   w_rw1, n_w1},  {right_w2,   w_rw2, n_w2},
            {child,      pch,   NSEQ * Dm}, {parent, pph,   Bm * Dm},
        };
        CvtArgs ca;
        int acc = 0;
        for (int i = 0; i < 12; i++) {
            ca.src[i] = (const float2*)segs[i].s;
            ca.dst[i] = (__half2*)segs[i].d;
            acc += segs[i].n / 2;
            ca.end[i] = acc;
        }
        cvt_all<<<(acc + 255) / 256, 256>>>(ca, acc);
    }

    // pe @ W{q,k}^T biases
    peb<<<(2 * Lm * 3 * Dm * 32) / 256, 256>>>(pos_emb, w_aiw, ppeq, ppek);

    const int EW = (TT * Dm) / 256;
    build_x<<<EW, 256>>>(parent, child);

    // ---- outside-score path (2 batched launches) ----
    {
        __half* h_lft = pah;                              // 8192 x 768
        __half* h_rgt = pah + (size_t)8192 * Dm;
        __half* h_par = pah + (size_t)16384 * Dm;         // 256 x 768
        float*  o_lc  = pt;                               // 8192 x 512
        float*  o_rc  = pt + (size_t)8192 * CSm;
        float*  o_pc  = pt + (size_t)16384 * CSm;         // 256 x 512

        hgemm_b3<true, true><<<dim3(3, 130), 256, SMEMB>>>(
            pch,      2 * Dm, w_lw1, left_b1,   h_lft,
            pch + Dm, 2 * Dm, w_rw1, right_b1,  h_rgt,
            pph,      Dm,     w_pw1, parent_b1, h_par,
            64, 128, Dm, Dm);
        hgemm_b3<false, false><<<dim3(2, 130), 256, SMEMB>>>(
            h_lft, Dm, w_lw2, left_b2,   o_lc,
            h_rgt, Dm, w_rw2, right_b2,  o_rc,
            h_par, Dm, w_pw2, parent_b2, o_pc,
            64, 128, CSm, Dm);
        dot_scores<<<(NSEQ * 32) / 256, 256>>>(o_pc, o_lc, o_rc, out);
    }

    // ---- 3 tree-transformer layers ----
    dim3 gQKV(QKV / 256, TT / 128);    // (9, 256)
    dim3 gD  (Dm  / 256, TT / 128);    // (3, 256)
    dim3 gM1 (FFm / 256, TT / 128);    // (12, 256)
    __half* pqkv_p = pqkv + (size_t)NSEQ * QKV;   // parent QKV (layer 1)

    for (int l = 0; l < Lm; l++) {
        const __half* iw = w_aiw + (size_t)l * 3 * Dm * Dm;
        const float*  ib = attn_in_b  + (size_t)l * 3 * Dm;
        const __half* ow = w_aow + (size_t)l * Dm * Dm;
        const float*  ob = attn_out_b + (size_t)l * Dm;
        const __half* w1 = w_l1  + (size_t)l * FFm * Dm;
        const float*  b1 = lin1_b     + (size_t)l * FFm;
        const __half* w2 = w_l2  + (size_t)l * Dm * FFm;
        const float*  b2 = lin2_b     + (size_t)l * Dm;

        if (l == 0) {
            // deduped QKV: child rows (16384) + parent rows (256)
            hgemm_b3<false, true><<<dim3(QKV / 256, 130), 256, SMEMB>>>(
                pch, Dm, iw, ib, pqkv,
                pph, Dm, iw, ib, pqkv_p,
                pph, Dm, iw, ib, pqkv_p,      // unused segment
                128, 130, QKV, Dm);
            attn2<true><<<(NSEQ * Hm * 32) / 256, 256>>>(pqkv, pqkv_p, ppeq, ppek);
        } else {
            hgemm<false, true><<<gQKV, 256, SMEMB>>>(pxh, Dm, iw, ib, pqkv, QKV, Dm);
            attn2<false><<<(NSEQ * Hm * 32) / 256, 256>>>(
                pqkv, pqkv,
                ppeq + (size_t)l * 3 * Dm, ppek + (size_t)l * 3 * Dm);
        }
        hgemm<false, false><<<gD , 256, SMEMB>>>(pah, Dm, ow, ob, pt, Dm, Dm);
        add_inorm<<<(TT * 32) / 256, 256>>>(px, pxh, pt);
        hgemm<true , true ><<<gM1, 256, SMEMB>>>(pxh,  Dm,  w1, b1, phid, FFm, Dm);
        hgemm<false, false><<<gD , 256, SMEMB>>>(phid, FFm, w2, b2, pt,   Dm,  FFm);
        add_inorm<<<(TT * 32) / 256, 256>>>(px, pxh, pt);
    }

    final_out<<<(NSEQ * 32) / 256, 256>>>(out + NSEQ);
}